// round 11
// baseline (speedup 1.0000x reference)
#include <cuda_runtime.h>
#include <cuda_bf16.h>
#include <cstdint>

// Problem constants
#define BB 4
#define SS 2048
#define HH 1024
#define NH 16
#define HD 64
#define NROWS (BB*SS)          // 8192
#define CHUNK 64
#define NCHUNK (SS/CHUNK)      // 32
#define BHDIM (BB*NH)          // 64
#define SE (HD*HD)             // 4096

// ---------------- scratch (static __device__, allocation-free) ----------------
__device__ __align__(16) float g_q[(size_t)NROWS*HH];
__device__ __align__(16) float g_k[(size_t)NROWS*HH];
__device__ __align__(16) float g_v[(size_t)NROWS*HH];
__device__ __align__(16) float g_g[(size_t)NROWS*HH];
__device__ __align__(16) float g_attn[(size_t)NROWS*HH];
__device__ float g_alpha[NROWS*NH];
__device__ float g_beta[NROWS*NH];
__device__ __align__(16) float g_M [(size_t)BHDIM*NCHUNK*SE];
__device__ __align__(16) float g_Cc[(size_t)BHDIM*NCHUNK*SE];
__device__ __align__(16) float g_S0[(size_t)BHDIM*NCHUNK*SE];

// bf16 split buffers
__device__ __align__(16) __nv_bfloat16 g_xhi[(size_t)NROWS*HH];
__device__ __align__(16) __nv_bfloat16 g_xlo[(size_t)NROWS*HH];
__device__ __align__(16) __nv_bfloat16 g_whi[(size_t)5*HH*HH];
__device__ __align__(16) __nv_bfloat16 g_wlo[(size_t)5*HH*HH];
__device__ __align__(16) __nv_bfloat16 g_ahi[(size_t)NROWS*HH];
__device__ __align__(16) __nv_bfloat16 g_alo[(size_t)NROWS*HH];
__device__ __align__(16) __nv_bfloat16 g_abhi[2*NH*HH];
__device__ __align__(16) __nv_bfloat16 g_ablo[2*NH*HH];

__device__ __forceinline__ float sigmoidf_(float z){ return 1.f/(1.f+expf(-z)); }

__device__ __forceinline__ void split4(float4 v, __nv_bfloat16* hi, __nv_bfloat16* lo){
    float f[4] = {v.x, v.y, v.z, v.w};
    __nv_bfloat16 h[4], l[4];
    #pragma unroll
    for (int j=0;j<4;j++){
        h[j] = __float2bfloat16_rn(f[j]);
        l[j] = __float2bfloat16_rn(f[j] - __bfloat162float(h[j]));
    }
    reinterpret_cast<__nv_bfloat162*>(hi)[0] = __halves2bfloat162(h[0], h[1]);
    reinterpret_cast<__nv_bfloat162*>(hi)[1] = __halves2bfloat162(h[2], h[3]);
    reinterpret_cast<__nv_bfloat162*>(lo)[0] = __halves2bfloat162(l[0], l[1]);
    reinterpret_cast<__nv_bfloat162*>(lo)[1] = __halves2bfloat162(l[2], l[3]);
}

// ---------------- fused fp32 -> bf16 hi/lo split (x | 5 W | Wab) -------------
#define XN4 ((NROWS*HH)/4)      // 2097152
#define WN4 ((HH*HH)/4)         // 262144
#define QN4 ((NH*HH)/4)         // 4096
#define CVT_TOT (XN4 + 5*WN4 + 2*QN4)

__global__ void __launch_bounds__(256) cvt_all_kernel(
    const float* __restrict__ x,
    const float* __restrict__ W0, const float* __restrict__ W1,
    const float* __restrict__ W2, const float* __restrict__ W3,
    const float* __restrict__ W4,
    const float* __restrict__ Wa, const float* __restrict__ Wb)
{
    const int i = blockIdx.x*256 + threadIdx.x;
    if (i >= CVT_TOT) return;
    if (i < XN4){
        split4(reinterpret_cast<const float4*>(x)[i], g_xhi + 4*(size_t)i, g_xlo + 4*(size_t)i);
    } else if (i < XN4 + 5*WN4){
        const int j5 = i - XN4;
        const int mat = j5 / WN4, j = j5 - mat*WN4;
        const float* src;
        switch (mat){
            case 0: src = W0; break; case 1: src = W1; break;
            case 2: src = W2; break; case 3: src = W3; break;
            default: src = W4; break;
        }
        const size_t o = (size_t)mat*HH*HH + 4*(size_t)j;
        split4(reinterpret_cast<const float4*>(src)[j], g_whi + o, g_wlo + o);
    } else {
        const int j = i - XN4 - 5*WN4;
        float4 v = (j < QN4) ? reinterpret_cast<const float4*>(Wa)[j]
                             : reinterpret_cast<const float4*>(Wb)[j-QN4];
        split4(v, g_abhi + 4*(size_t)j, g_ablo + 4*(size_t)j);
    }
}

// ---------------- common mma/ldsm/cp helpers ---------------------------------
__device__ __forceinline__ void cp16(uint32_t smem, const void* gptr){
    const unsigned long long g = (unsigned long long)__cvta_generic_to_global(gptr);
    asm volatile("cp.async.cg.shared.global [%0], [%1], 16;" :: "r"(smem), "l"(g) : "memory");
}

__device__ __forceinline__ void mma16816(float* c, const uint32_t* a, const uint32_t* b){
    asm volatile("mma.sync.aligned.m16n8k16.row.col.f32.bf16.bf16.f32 "
        "{%0,%1,%2,%3}, {%4,%5,%6,%7}, {%8,%9}, {%0,%1,%2,%3};"
        : "+f"(c[0]), "+f"(c[1]), "+f"(c[2]), "+f"(c[3])
        : "r"(a[0]), "r"(a[1]), "r"(a[2]), "r"(a[3]), "r"(b[0]), "r"(b[1]));
}

__device__ __forceinline__ void ldsm4(uint32_t* r, uint32_t addr){
    asm volatile("ldmatrix.sync.aligned.m8n8.x4.shared.b16 {%0,%1,%2,%3}, [%4];"
        : "=r"(r[0]), "=r"(r[1]), "=r"(r[2]), "=r"(r[3]) : "r"(addr));
}

// ---------------- alpha/beta GEMM body (runs inside mm0 grid) ----------------
#define ABSTAGE 25600
#define ABNKT (HH/32)

__device__ void ab_mma_body(__nv_bfloat16* smem_ab,
                            const float* __restrict__ ba, const float* __restrict__ bb)
{
    const uint32_t sba = (uint32_t)__cvta_generic_to_shared(smem_ab);
    const int tid = threadIdx.x;
    const int wid = tid >> 5, lid = tid & 31;
    const int g = lid >> 2, tg = lid & 3;
    const int m0 = blockIdx.y * 128;

    float acc[4][4];
    #pragma unroll
    for (int a=0;a<4;a++)
        #pragma unroll
        for (int b=0;b<4;b++) acc[a][b] = 0.f;

    const uint32_t laneA = (uint32_t)((lid & 15)*80 + (lid >> 4)*16);
    const uint32_t laneB = (uint32_t)((((lid >> 4) & 1)*8 + (lid & 7))*80 + ((lid >> 3) & 1)*16);

    auto load_stage = [&](int kt){
        const uint32_t sb2 = sba + (uint32_t)((kt & 1) * ABSTAGE);
        const int k0 = kt * 32;
        for (int idx = tid; idx < 1280; idx += 256){
            uint32_t dst; const __nv_bfloat16* src; size_t off;
            if (idx < 512){
                const int r = idx >> 2, c = idx & 3;
                dst = sb2 + (uint32_t)(r*80 + c*16);
                src = g_xhi; off = (size_t)(m0 + r)*HH + k0 + c*8;
            } else if (idx < 1024){
                const int q = idx - 512, r = q >> 2, c = q & 3;
                dst = sb2 + 10240 + (uint32_t)(r*80 + c*16);
                src = g_xlo; off = (size_t)(m0 + r)*HH + k0 + c*8;
            } else if (idx < 1152){
                const int q = idx - 1024, r = q >> 2, c = q & 3;
                dst = sb2 + 20480 + (uint32_t)(r*80 + c*16);
                src = g_abhi; off = (size_t)r*HH + k0 + c*8;
            } else {
                const int q = idx - 1152, r = q >> 2, c = q & 3;
                dst = sb2 + 23040 + (uint32_t)(r*80 + c*16);
                src = g_ablo; off = (size_t)r*HH + k0 + c*8;
            }
            cp16(dst, src + off);
        }
        asm volatile("cp.async.commit_group;" ::: "memory");
    };

    load_stage(0);

    for (int kt = 0; kt < ABNKT; ++kt){
        if (kt + 1 < ABNKT) load_stage(kt + 1);
        if (kt + 1 < ABNKT) asm volatile("cp.async.wait_group 1;" ::: "memory");
        else                asm volatile("cp.async.wait_group 0;" ::: "memory");
        __syncthreads();

        const uint32_t base = sba + (uint32_t)((kt & 1) * ABSTAGE);
        const uint32_t aAh = base +         laneA + (uint32_t)(wid*16)*80;
        const uint32_t aAl = base + 10240 + laneA + (uint32_t)(wid*16)*80;
        const uint32_t aBh = base + 20480 + laneB;
        const uint32_t aBl = base + 23040 + laneB;

        #pragma unroll
        for (int ks = 0; ks < 2; ++ks){
            const uint32_t kb = (uint32_t)(ks*32);
            uint32_t bh[4][2], bl[4][2];
            {
                uint32_t r[4];
                ldsm4(r, aBh + kb);
                bh[0][0]=r[0]; bh[0][1]=r[1]; bh[1][0]=r[2]; bh[1][1]=r[3];
                ldsm4(r, aBh + kb + 16*80);
                bh[2][0]=r[0]; bh[2][1]=r[1]; bh[3][0]=r[2]; bh[3][1]=r[3];
                ldsm4(r, aBl + kb);
                bl[0][0]=r[0]; bl[0][1]=r[1]; bl[1][0]=r[2]; bl[1][1]=r[3];
                ldsm4(r, aBl + kb + 16*80);
                bl[2][0]=r[0]; bl[2][1]=r[1]; bl[3][0]=r[2]; bl[3][1]=r[3];
            }
            uint32_t af[4];
            ldsm4(af, aAh + kb);
            #pragma unroll
            for (int nt = 0; nt < 4; ++nt){
                mma16816(acc[nt], af, bh[nt]);
                mma16816(acc[nt], af, bl[nt]);
            }
            ldsm4(af, aAl + kb);
            #pragma unroll
            for (int nt = 0; nt < 4; ++nt)
                mma16816(acc[nt], af, bh[nt]);
        }
        __syncthreads();
    }

    const int r0 = m0 + wid*16 + g;
    #pragma unroll
    for (int nt = 0; nt < 4; ++nt){
        const int n = nt*8 + 2*tg;
        #pragma unroll
        for (int e = 0; e < 2; ++e){
            const int nn = n + e;
            const float bias = (nn < NH) ? ba[nn] : bb[nn - NH];
            float v0 = sigmoidf_(acc[nt][e]     + bias);
            float v1 = sigmoidf_(acc[nt][e + 2] + bias);
            if (nn < NH){
                g_alpha[r0*NH + nn]     = v0;
                g_alpha[(r0+8)*NH + nn] = v1;
            } else {
                g_beta[r0*NH + nn - NH]     = v0;
                g_beta[(r0+8)*NH + nn - NH] = v1;
            }
        }
    }
}

// ---------------- main GEMM: K32, 2-stage, ldmatrix, occ 2, 1 sync/iter ------
#define SROW 40                 // bf16 elems per smem row (80 B)
#define STG  (128*SROW)         // elems per matrix region per stage
#define NKT  (HH/32)            // 32 K-stages
#define MM_SMEM (2*4*STG*2)     // 81920 B

__global__ void __launch_bounds__(256, 2) mm_kernel(int mode, float* __restrict__ Cext,
                                                    const float* __restrict__ ba,
                                                    const float* __restrict__ bb)
{
    extern __shared__ __align__(16) __nv_bfloat16 smem_bf[];

    // merged alpha/beta GEMM: extra x-slice of the mode-0 grid
    if (mode == 0 && blockIdx.x == 32){
        ab_mma_body(smem_bf, ba, bb);
        return;
    }

    const uint32_t sba = (uint32_t)__cvta_generic_to_shared(smem_bf);
    const int tid = threadIdx.x;
    const int wid = tid >> 5, lid = tid & 31;
    const int g = lid >> 2, tg = lid & 3;
    const int wm = wid & 1, wn = wid >> 1;

    const int m0 = blockIdx.y * 128;
    const int n0 = blockIdx.x * 128;
    const int wrow = (mode ? 4096 : 0) + n0;
    const __nv_bfloat16* Ah = mode ? g_ahi : g_xhi;
    const __nv_bfloat16* Al = mode ? g_alo : g_xlo;

    float acc[4][4][4];
    #pragma unroll
    for (int a=0;a<4;a++)
        #pragma unroll
        for (int b=0;b<4;b++)
            #pragma unroll
            for (int c=0;c<4;c++) acc[a][b][c] = 0.f;

    const uint32_t laneA = (uint32_t)((lid & 15)*80 + (lid >> 4)*16);
    const uint32_t laneB = (uint32_t)((((lid >> 4) & 1)*8 + (lid & 7))*80 + ((lid >> 3) & 1)*16);

    const int ch0row = tid >> 2,        ch0c = (tid & 3);
    const int ch1row = (tid+256) >> 2,  ch1c = ((tid+256) & 3);

    auto load_stage = [&](int kt){
        const uint32_t sb2 = sba + (uint32_t)((kt & 1) * 4 * STG) * 2;
        const int k0 = kt * 32;
        {
            const int row = ch0row, c16 = ch0c;
            const uint32_t d = (uint32_t)(row*SROW + c16*8) * 2;
            const size_t ka = (size_t)k0 + c16*8;
            const size_t aoff = (size_t)(m0 + row)*HH + ka;
            const size_t boff = (size_t)(wrow + row)*HH + ka;
            cp16(sb2 + d,             Ah    + aoff);
            cp16(sb2 + STG*2 + d,     Al    + aoff);
            cp16(sb2 + 2*STG*2 + d,   g_whi + boff);
            cp16(sb2 + 3*STG*2 + d,   g_wlo + boff);
        }
        {
            const int row = ch1row, c16 = ch1c;
            const uint32_t d = (uint32_t)(row*SROW + c16*8) * 2;
            const size_t ka = (size_t)k0 + c16*8;
            const size_t aoff = (size_t)(m0 + row)*HH + ka;
            const size_t boff = (size_t)(wrow + row)*HH + ka;
            cp16(sb2 + d,             Ah    + aoff);
            cp16(sb2 + STG*2 + d,     Al    + aoff);
            cp16(sb2 + 2*STG*2 + d,   g_whi + boff);
            cp16(sb2 + 3*STG*2 + d,   g_wlo + boff);
        }
        asm volatile("cp.async.commit_group;" ::: "memory");
    };

    load_stage(0);

    for (int kt = 0; kt < NKT; ++kt){
        asm volatile("cp.async.wait_group 0;" ::: "memory");
        __syncthreads();
        // single sync proves stage-kt visibility AND that all warps finished kt-1.
        if (kt + 1 < NKT) load_stage(kt + 1);   // start next DMA as early as possible

        const uint32_t stgb = sba + (uint32_t)((kt & 1) * 4 * STG) * 2;
        const uint32_t aAh = stgb +             laneA + (uint32_t)(wm*64)*80;
        const uint32_t aAl = stgb + STG*2     + laneA + (uint32_t)(wm*64)*80;
        const uint32_t aBh = stgb + 2*STG*2   + laneB + (uint32_t)(wn*32)*80;
        const uint32_t aBl = stgb + 3*STG*2   + laneB + (uint32_t)(wn*32)*80;

        uint32_t bh[2][4][2], bl[2][4][2];
        #pragma unroll
        for (int ks = 0; ks < 2; ++ks){
            const uint32_t kb = (uint32_t)(ks*32);
            uint32_t r[4];
            ldsm4(r, aBh + kb);
            bh[ks][0][0]=r[0]; bh[ks][0][1]=r[1]; bh[ks][1][0]=r[2]; bh[ks][1][1]=r[3];
            ldsm4(r, aBh + kb + 16*80);
            bh[ks][2][0]=r[0]; bh[ks][2][1]=r[1]; bh[ks][3][0]=r[2]; bh[ks][3][1]=r[3];
            ldsm4(r, aBl + kb);
            bl[ks][0][0]=r[0]; bl[ks][0][1]=r[1]; bl[ks][1][0]=r[2]; bl[ks][1][1]=r[3];
            ldsm4(r, aBl + kb + 16*80);
            bl[ks][2][0]=r[0]; bl[ks][2][1]=r[1]; bl[ks][3][0]=r[2]; bl[ks][3][1]=r[3];
        }

        #pragma unroll
        for (int ks = 0; ks < 2; ++ks){
            const uint32_t kb = (uint32_t)(ks*32);
            #pragma unroll
            for (int mt = 0; mt < 4; ++mt){
                uint32_t af[4];
                ldsm4(af, aAh + kb + (uint32_t)(mt*16)*80);
                #pragma unroll
                for (int nt = 0; nt < 4; ++nt){
                    mma16816(acc[mt][nt], af, bh[ks][nt]);
                    mma16816(acc[mt][nt], af, bl[ks][nt]);
                }
                ldsm4(af, aAl + kb + (uint32_t)(mt*16)*80);
                #pragma unroll
                for (int nt = 0; nt < 4; ++nt)
                    mma16816(acc[mt][nt], af, bh[ks][nt]);
            }
        }
    }

    float* dst; int epi = 0; int colb;
    if (mode == 0){
        const int mat = n0 >> 10;
        colb = n0 & 1023;
        switch (mat){
            case 0: dst = g_q; break;
            case 1: dst = g_k; break;
            case 2: dst = g_v; epi = 1; break;
            default: dst = g_g; epi = 1; break;
        }
    } else { dst = Cext; colb = n0; }

    #pragma unroll
    for (int mt = 0; mt < 4; ++mt){
        const int r = m0 + wm*64 + mt*16 + g;
        #pragma unroll
        for (int nt = 0; nt < 4; ++nt){
            const int cidx = colb + wn*32 + nt*8 + 2*tg;
            float v0 = acc[mt][nt][0], v1 = acc[mt][nt][1];
            float v2 = acc[mt][nt][2], v3 = acc[mt][nt][3];
            if (epi){
                v0 *= sigmoidf_(v0); v1 *= sigmoidf_(v1);
                v2 *= sigmoidf_(v2); v3 *= sigmoidf_(v3);
            }
            *reinterpret_cast<float2*>(dst + (size_t)r*HH + cidx)     = make_float2(v0, v1);
            *reinterpret_cast<float2*>(dst + (size_t)(r+8)*HH + cidx) = make_float2(v2, v3);
        }
    }
}

// ---------------- in-smem per-row L2 normalize helper -------------------------
__device__ __forceinline__ void l2norm_smem(float* buf, int w, int l)
{
    const int row = w*4 + (l >> 3);
    const int col = (l & 7) * 8;
    float* p = buf + row*HD + col;
    const float4 a0 = *reinterpret_cast<const float4*>(p);
    const float4 a1 = *reinterpret_cast<const float4*>(p + 4);
    float ss = a0.x*a0.x + a0.y*a0.y + a0.z*a0.z + a0.w*a0.w
             + a1.x*a1.x + a1.y*a1.y + a1.z*a1.z + a1.w*a1.w;
    ss += __shfl_xor_sync(0xffffffffu, ss, 1);
    ss += __shfl_xor_sync(0xffffffffu, ss, 2);
    ss += __shfl_xor_sync(0xffffffffu, ss, 4);
    const float inv = 1.f / fmaxf(sqrtf(ss), 1e-12f);
    *reinterpret_cast<float4*>(p)     = make_float4(a0.x*inv, a0.y*inv, a0.z*inv, a0.w*inv);
    *reinterpret_cast<float4*>(p + 4) = make_float4(a1.x*inv, a1.y*inv, a1.z*inv, a1.w*inv);
}

// ---------------- recurrence pass 1 (fused k-normalization) -------------------
__global__ void __launch_bounds__(512) pass1_kernel()
{
    const int c = blockIdx.x, bh = blockIdx.y;
    const int b = bh >> 4, h = bh & 15;
    const int tid = threadIdx.x;
    const int w = tid >> 5, l = tid & 31;
    __shared__ __align__(16) float ks[CHUNK*HD];
    __shared__ __align__(16) float vs[CHUNK*HD];
    __shared__ float aa[CHUNK], bbs[CHUNK];

    const int row0 = b*SS + c*CHUNK;
    for (int idx = tid; idx < CHUNK*16; idx += 512){
        const int t = idx >> 4, c4 = (idx & 15) * 4;
        const size_t go = (size_t)(row0 + t)*HH + h*HD + c4;
        *reinterpret_cast<float4*>(&ks[t*HD + c4]) = *reinterpret_cast<const float4*>(&g_k[go]);
        *reinterpret_cast<float4*>(&vs[t*HD + c4]) = *reinterpret_cast<const float4*>(&g_v[go]);
    }
    if (tid < CHUNK){
        aa[tid]  = g_alpha[(row0 + tid)*NH + h];
        bbs[tid] = g_beta [(row0 + tid)*NH + h];
    }
    __syncthreads();
    l2norm_smem(ks, w, l);
    __syncthreads();

    float M[4][2], Cc[4][2];
    #pragma unroll
    for (int r=0;r<4;r++){ M[r][0]=1.f; M[r][1]=1.f; Cc[r][0]=0.f; Cc[r][1]=0.f; }

    #pragma unroll 2
    for (int t=0;t<CHUNK;++t){
        const float a = aa[t], bt = bbs[t], abp = a*bt;
        const float kj0 = ks[t*HD + l], kj1 = ks[t*HD + l + 32];
        #pragma unroll
        for (int r=0;r<4;r++){
            const int i = w*4 + r;
            const float ki = ks[t*HD + i];
            const float bvi = bt * vs[t*HD + i];
            const float abki = abp * ki;
            const float m0 = fmaf(-abki, kj0, a);
            const float m1 = fmaf(-abki, kj1, a);
            M[r][0] *= m0;  M[r][1] *= m1;
            Cc[r][0] = fmaf(m0, Cc[r][0], bvi*kj0);
            Cc[r][1] = fmaf(m1, Cc[r][1], bvi*kj1);
        }
    }
    const size_t ob = ((size_t)bh*NCHUNK + c) * SE;
    #pragma unroll
    for (int r=0;r<4;r++){
        const int i = w*4 + r;
        g_M [ob + i*HD + l]      = M[r][0];
        g_M [ob + i*HD + l + 32] = M[r][1];
        g_Cc[ob + i*HD + l]      = Cc[r][0];
        g_Cc[ob + i*HD + l + 32] = Cc[r][1];
    }
}

// ---------------- serial scan over chunks (128 blocks, 4 chains/thread) ------
__global__ void __launch_bounds__(512) scan_kernel()
{
    const int bh = blockIdx.x >> 1, part = blockIdx.x & 1;
    const size_t base = (size_t)bh * NCHUNK * SE + part*2048 + threadIdx.x;
    float s[4];
    #pragma unroll
    for (int u=0;u<4;u++) s[u] = 0.f;
    for (int c=0;c<NCHUNK;++c){
        const size_t cb = base + (size_t)c*SE;
        #pragma unroll
        for (int u=0;u<4;u++){
            const size_t idx = cb + (size_t)u*512;
            g_S0[idx] = s[u];
            s[u] = fmaf(g_M[idx], s[u], g_Cc[idx]);
        }
    }
}

// ---------------- recurrence pass 2 (fused k,q normalization) -----------------
#define P2_SMEM (4*CHUNK*HD*4 + 2*CHUNK*4)   // 66048 B
__global__ void __launch_bounds__(512) pass2_kernel()
{
    const int c = blockIdx.x, bh = blockIdx.y;
    const int b = bh >> 4, h = bh & 15;
    const int tid = threadIdx.x;
    const int w = tid >> 5, l = tid & 31;
    extern __shared__ __align__(16) float p2s[];
    float* ks  = p2s;
    float* vs  = p2s + CHUNK*HD;
    float* qs  = p2s + 2*CHUNK*HD;
    float* outs= p2s + 3*CHUNK*HD;
    float* aa  = p2s + 4*CHUNK*HD;
    float* bbs = aa + CHUNK;

    const int row0 = b*SS + c*CHUNK;
    for (int idx = tid; idx < CHUNK*16; idx += 512){
        const int t = idx >> 4, c4 = (idx & 15) * 4;
        const size_t go = (size_t)(row0 + t)*HH + h*HD + c4;
        *reinterpret_cast<float4*>(&ks[t*HD + c4]) = *reinterpret_cast<const float4*>(&g_k[go]);
        *reinterpret_cast<float4*>(&vs[t*HD + c4]) = *reinterpret_cast<const float4*>(&g_v[go]);
        *reinterpret_cast<float4*>(&qs[t*HD + c4]) = *reinterpret_cast<const float4*>(&g_q[go]);
    }
    if (tid < CHUNK){
        aa[tid]  = g_alpha[(row0 + tid)*NH + h];
        bbs[tid] = g_beta [(row0 + tid)*NH + h];
    }

    float st[4][2];
    const size_t sbg = ((size_t)bh*NCHUNK + c) * SE;
    #pragma unroll
    for (int r=0;r<4;r++){
        const int i = w*4 + r;
        st[r][0] = g_S0[sbg + i*HD + l];
        st[r][1] = g_S0[sbg + i*HD + l + 32];
    }
    __syncthreads();
    l2norm_smem(ks, w, l);
    l2norm_smem(qs, w, l);
    __syncthreads();

    #pragma unroll 2
    for (int t=0;t<CHUNK;++t){
        const float a = aa[t], bt = bbs[t], abp = a*bt;
        const float kj0 = ks[t*HD + l], kj1 = ks[t*HD + l + 32];
        const float qj0 = qs[t*HD + l], qj1 = qs[t*HD + l + 32];
        float p[4];
        #pragma unroll
        for (int r=0;r<4;r++){
            const int i = w*4 + r;
            const float ki = ks[t*HD + i];
            const float bvi = bt * vs[t*HD + i];
            const float abki = abp * ki;
            const float m0 = fmaf(-abki, kj0, a);
            const float m1 = fmaf(-abki, kj1, a);
            st[r][0] = fmaf(m0, st[r][0], bvi*kj0);
            st[r][1] = fmaf(m1, st[r][1], bvi*kj1);
            p[r] = fmaf(st[r][0], qj0, st[r][1]*qj1);
        }
        #pragma unroll
        for (int o=16;o;o>>=1){
            p[0] += __shfl_xor_sync(0xffffffffu, p[0], o);
            p[1] += __shfl_xor_sync(0xffffffffu, p[1], o);
            p[2] += __shfl_xor_sync(0xffffffffu, p[2], o);
            p[3] += __shfl_xor_sync(0xffffffffu, p[3], o);
        }
        if (l < 4) outs[t*HD + w*4 + l] = p[l];
    }
    __syncthreads();
    for (int idx = tid; idx < CHUNK*16; idx += 512){
        const int t = idx >> 4, c4 = (idx & 15) * 4;
        const size_t go = (size_t)(row0 + t)*HH + h*HD + c4;
        *reinterpret_cast<float4*>(&g_attn[go]) = *reinterpret_cast<const float4*>(&outs[t*HD + c4]);
    }
}

// ---------------- LayerNorm + SiLU-gate + bf16 split (fused) -----------------
__global__ void __launch_bounds__(256) ln_gate_kernel(
    const float* __restrict__ lng, const float* __restrict__ lnb)
{
    const int r = blockIdx.x, tid = threadIdx.x;
    __shared__ float xs[HH];
    __shared__ float red[8];
    const float* row = g_attn + (size_t)r*HH;
    float s = 0.f;
    for (int i=tid;i<HH;i+=256){ float v = row[i]; xs[i] = v; s += v; }
    #pragma unroll
    for (int o=16;o;o>>=1) s += __shfl_xor_sync(0xffffffffu, s, o);
    if ((tid & 31) == 0) red[tid>>5] = s;
    __syncthreads();
    float tot = red[0]+red[1]+red[2]+red[3]+red[4]+red[5]+red[6]+red[7];
    const float mu = tot * (1.f/HH);
    __syncthreads();
    float vsum = 0.f;
    for (int i=tid;i<HH;i+=256){ float d = xs[i]-mu; vsum = fmaf(d,d,vsum); }
    #pragma unroll
    for (int o=16;o;o>>=1) vsum += __shfl_xor_sync(0xffffffffu, vsum, o);
    if ((tid & 31) == 0) red[tid>>5] = vsum;
    __syncthreads();
    float vtot = red[0]+red[1]+red[2]+red[3]+red[4]+red[5]+red[6]+red[7];
    const float rstd = rsqrtf(vtot*(1.f/HH) + 1e-5f);
    for (int i=tid*4;i<HH;i+=256*4){
        float4 gv = *reinterpret_cast<const float4*>(g_g + (size_t)r*HH + i);
        float4 yv;
        yv.x = ((xs[i+0]-mu)*rstd*lng[i+0] + lnb[i+0]) * gv.x;
        yv.y = ((xs[i+1]-mu)*rstd*lng[i+1] + lnb[i+1]) * gv.y;
        yv.z = ((xs[i+2]-mu)*rstd*lng[i+2] + lnb[i+2]) * gv.z;
        yv.w = ((xs[i+3]-mu)*rstd*lng[i+3] + lnb[i+3]) * gv.w;
        split4(yv, g_ahi + (size_t)r*HH + i, g_alo + (size_t)r*HH + i);
    }
}

// ---------------- launch -----------------------------------------------------
extern "C" void kernel_launch(void* const* d_in, const int* in_sizes, int n_in,
                              void* d_out, int out_size)
{
    const float* x   = (const float*)d_in[0];
    const float* Wq  = (const float*)d_in[1];
    const float* Wk  = (const float*)d_in[2];
    const float* Wv  = (const float*)d_in[3];
    const float* Wa  = (const float*)d_in[4];
    const float* ba  = (const float*)d_in[5];
    const float* Wb  = (const float*)d_in[6];
    const float* bb  = (const float*)d_in[7];
    const float* Wg  = (const float*)d_in[8];
    const float* Wo  = (const float*)d_in[9];
    const float* lng = (const float*)d_in[10];
    const float* lnb = (const float*)d_in[11];
    float* out = (float*)d_out;

    cudaFuncSetAttribute(mm_kernel, cudaFuncAttributeMaxDynamicSharedMemorySize, MM_SMEM);
    cudaFuncSetAttribute(pass2_kernel, cudaFuncAttributeMaxDynamicSharedMemorySize, P2_SMEM);

    cvt_all_kernel<<<(CVT_TOT+255)/256, 256>>>(x, Wq, Wk, Wv, Wg, Wo, Wa, Wb);
    mm_kernel<<<dim3(33, 64), 256, MM_SMEM>>>(0, nullptr, ba, bb);  // QKVG + alpha/beta
    pass1_kernel<<<dim3(NCHUNK, BHDIM), 512>>>();
    scan_kernel<<<2*BHDIM, 512>>>();
    pass2_kernel<<<dim3(NCHUNK, BHDIM), 512, P2_SMEM>>>();
    ln_gate_kernel<<<NROWS, 256>>>(lng, lnb);
    mm_kernel<<<dim3(8, 64), 256, MM_SMEM>>>(1, out, nullptr, nullptr);
}

// round 12
// speedup vs baseline: 1.2355x; 1.2355x over previous
#include <cuda_runtime.h>
#include <cuda_fp16.h>
#include <cstdint>

// Problem constants
#define BB 4
#define SS 2048
#define HH 1024
#define NH 16
#define HD 64
#define NROWS (BB*SS)          // 8192
#define CHUNK 64
#define NCHUNK (SS/CHUNK)      // 32
#define BHDIM (BB*NH)          // 64
#define SE (HD*HD)             // 4096

// ---------------- scratch (static __device__, allocation-free) ----------------
__device__ __align__(16) float g_q[(size_t)NROWS*HH];
__device__ __align__(16) float g_k[(size_t)NROWS*HH];
__device__ __align__(16) float g_v[(size_t)NROWS*HH];
__device__ __align__(16) float g_g[(size_t)NROWS*HH];
__device__ __align__(16) float g_attn[(size_t)NROWS*HH];
__device__ float g_alpha[NROWS*NH];
__device__ float g_beta[NROWS*NH];
__device__ __align__(16) float g_M [(size_t)BHDIM*NCHUNK*SE];
__device__ __align__(16) float g_Cc[(size_t)BHDIM*NCHUNK*SE];
__device__ __align__(16) float g_S0[(size_t)BHDIM*NCHUNK*SE];

// fp16 split buffers (A side: hi+lo; B side: hi only)
__device__ __align__(16) __half g_xhi[(size_t)NROWS*HH];
__device__ __align__(16) __half g_xlo[(size_t)NROWS*HH];
__device__ __align__(16) __half g_whi[(size_t)5*HH*HH];
__device__ __align__(16) __half g_ahi[(size_t)NROWS*HH];
__device__ __align__(16) __half g_alo[(size_t)NROWS*HH];
__device__ __align__(16) __half g_abhi[2*NH*HH];

__device__ __forceinline__ float sigmoidf_(float z){ return 1.f/(1.f+expf(-z)); }

__device__ __forceinline__ void split4h(float4 v, __half* hi, __half* lo){
    float f[4] = {v.x, v.y, v.z, v.w};
    __half h[4], l[4];
    #pragma unroll
    for (int j=0;j<4;j++){
        h[j] = __float2half_rn(f[j]);
        l[j] = __float2half_rn(f[j] - __half2float(h[j]));
    }
    reinterpret_cast<__half2*>(hi)[0] = __halves2half2(h[0], h[1]);
    reinterpret_cast<__half2*>(hi)[1] = __halves2half2(h[2], h[3]);
    reinterpret_cast<__half2*>(lo)[0] = __halves2half2(l[0], l[1]);
    reinterpret_cast<__half2*>(lo)[1] = __halves2half2(l[2], l[3]);
}

__device__ __forceinline__ void cvt4h(float4 v, __half* hi){
    reinterpret_cast<__half2*>(hi)[0] = __halves2half2(__float2half_rn(v.x), __float2half_rn(v.y));
    reinterpret_cast<__half2*>(hi)[1] = __halves2half2(__float2half_rn(v.z), __float2half_rn(v.w));
}

// ---------------- fused fp32 -> fp16 conversion (x split | 5 W hi | Wab hi) --
#define XN4 ((NROWS*HH)/4)      // 2097152
#define WN4 ((HH*HH)/4)         // 262144
#define QN4 ((NH*HH)/4)         // 4096
#define CVT_TOT (XN4 + 5*WN4 + 2*QN4)

__global__ void __launch_bounds__(256) cvt_all_kernel(
    const float* __restrict__ x,
    const float* __restrict__ W0, const float* __restrict__ W1,
    const float* __restrict__ W2, const float* __restrict__ W3,
    const float* __restrict__ W4,
    const float* __restrict__ Wa, const float* __restrict__ Wb)
{
    const int i = blockIdx.x*256 + threadIdx.x;
    if (i >= CVT_TOT) return;
    if (i < XN4){
        split4h(reinterpret_cast<const float4*>(x)[i], g_xhi + 4*(size_t)i, g_xlo + 4*(size_t)i);
    } else if (i < XN4 + 5*WN4){
        const int j5 = i - XN4;
        const int mat = j5 / WN4, j = j5 - mat*WN4;
        const float* src;
        switch (mat){
            case 0: src = W0; break; case 1: src = W1; break;
            case 2: src = W2; break; case 3: src = W3; break;
            default: src = W4; break;
        }
        cvt4h(reinterpret_cast<const float4*>(src)[j], g_whi + (size_t)mat*HH*HH + 4*(size_t)j);
    } else {
        const int j = i - XN4 - 5*WN4;
        float4 v = (j < QN4) ? reinterpret_cast<const float4*>(Wa)[j]
                             : reinterpret_cast<const float4*>(Wb)[j-QN4];
        cvt4h(v, g_abhi + 4*(size_t)j);
    }
}

// ---------------- common mma/ldsm/cp helpers ---------------------------------
__device__ __forceinline__ void cp16(uint32_t smem, const void* gptr){
    const unsigned long long g = (unsigned long long)__cvta_generic_to_global(gptr);
    asm volatile("cp.async.cg.shared.global [%0], [%1], 16;" :: "r"(smem), "l"(g) : "memory");
}

__device__ __forceinline__ void mma16816(float* c, const uint32_t* a, const uint32_t* b){
    asm volatile("mma.sync.aligned.m16n8k16.row.col.f32.f16.f16.f32 "
        "{%0,%1,%2,%3}, {%4,%5,%6,%7}, {%8,%9}, {%0,%1,%2,%3};"
        : "+f"(c[0]), "+f"(c[1]), "+f"(c[2]), "+f"(c[3])
        : "r"(a[0]), "r"(a[1]), "r"(a[2]), "r"(a[3]), "r"(b[0]), "r"(b[1]));
}

__device__ __forceinline__ void ldsm4(uint32_t* r, uint32_t addr){
    asm volatile("ldmatrix.sync.aligned.m8n8.x4.shared.b16 {%0,%1,%2,%3}, [%4];"
        : "=r"(r[0]), "=r"(r[1]), "=r"(r[2]), "=r"(r[3]) : "r"(addr));
}

// ---------------- alpha/beta GEMM body (runs inside mm0 grid) ----------------
// regions: Ah 10240 | Al 10240 | Bh 2560 per stage
#define ABSTG 23040
#define ABNKT (HH/32)

__device__ void ab_mma_body(__half* smem_ab,
                            const float* __restrict__ ba, const float* __restrict__ bb)
{
    const uint32_t sba = (uint32_t)__cvta_generic_to_shared(smem_ab);
    const int tid = threadIdx.x;
    const int wid = tid >> 5, lid = tid & 31;
    const int g = lid >> 2, tg = lid & 3;
    const int m0 = blockIdx.y * 128;

    float acc[4][4];
    #pragma unroll
    for (int a=0;a<4;a++)
        #pragma unroll
        for (int b=0;b<4;b++) acc[a][b] = 0.f;

    const uint32_t laneA = (uint32_t)((lid & 15)*80 + (lid >> 4)*16);
    const uint32_t laneB = (uint32_t)((((lid >> 4) & 1)*8 + (lid & 7))*80 + ((lid >> 3) & 1)*16);

    auto load_stage = [&](int kt){
        const uint32_t sb2 = sba + (uint32_t)((kt & 1) * ABSTG);
        const int k0 = kt * 32;
        for (int idx = tid; idx < 1152; idx += 256){
            uint32_t dst; const __half* src; size_t off;
            if (idx < 512){
                const int r = idx >> 2, c = idx & 3;
                dst = sb2 + (uint32_t)(r*80 + c*16);
                src = g_xhi; off = (size_t)(m0 + r)*HH + k0 + c*8;
            } else if (idx < 1024){
                const int q = idx - 512, r = q >> 2, c = q & 3;
                dst = sb2 + 10240 + (uint32_t)(r*80 + c*16);
                src = g_xlo; off = (size_t)(m0 + r)*HH + k0 + c*8;
            } else {
                const int q = idx - 1024, r = q >> 2, c = q & 3;
                dst = sb2 + 20480 + (uint32_t)(r*80 + c*16);
                src = g_abhi; off = (size_t)r*HH + k0 + c*8;
            }
            cp16(dst, src + off);
        }
        asm volatile("cp.async.commit_group;" ::: "memory");
    };

    load_stage(0);

    for (int kt = 0; kt < ABNKT; ++kt){
        if (kt + 1 < ABNKT) load_stage(kt + 1);
        if (kt + 1 < ABNKT) asm volatile("cp.async.wait_group 1;" ::: "memory");
        else                asm volatile("cp.async.wait_group 0;" ::: "memory");
        __syncthreads();

        const uint32_t base = sba + (uint32_t)((kt & 1) * ABSTG);
        const uint32_t aAh = base +         laneA + (uint32_t)(wid*16)*80;
        const uint32_t aAl = base + 10240 + laneA + (uint32_t)(wid*16)*80;
        const uint32_t aBh = base + 20480 + laneB;

        #pragma unroll
        for (int ks = 0; ks < 2; ++ks){
            const uint32_t kb = (uint32_t)(ks*32);
            uint32_t bh[4][2];
            {
                uint32_t r[4];
                ldsm4(r, aBh + kb);
                bh[0][0]=r[0]; bh[0][1]=r[1]; bh[1][0]=r[2]; bh[1][1]=r[3];
                ldsm4(r, aBh + kb + 16*80);
                bh[2][0]=r[0]; bh[2][1]=r[1]; bh[3][0]=r[2]; bh[3][1]=r[3];
            }
            uint32_t af[4];
            ldsm4(af, aAh + kb);
            #pragma unroll
            for (int nt = 0; nt < 4; ++nt)
                mma16816(acc[nt], af, bh[nt]);
            ldsm4(af, aAl + kb);
            #pragma unroll
            for (int nt = 0; nt < 4; ++nt)
                mma16816(acc[nt], af, bh[nt]);
        }
        __syncthreads();
    }

    const int r0 = m0 + wid*16 + g;
    #pragma unroll
    for (int nt = 0; nt < 4; ++nt){
        const int n = nt*8 + 2*tg;
        #pragma unroll
        for (int e = 0; e < 2; ++e){
            const int nn = n + e;
            const float bias = (nn < NH) ? ba[nn] : bb[nn - NH];
            float v0 = sigmoidf_(acc[nt][e]     + bias);
            float v1 = sigmoidf_(acc[nt][e + 2] + bias);
            if (nn < NH){
                g_alpha[r0*NH + nn]     = v0;
                g_alpha[(r0+8)*NH + nn] = v1;
            } else {
                g_beta[r0*NH + nn - NH]     = v0;
                g_beta[(r0+8)*NH + nn - NH] = v1;
            }
        }
    }
}

// ---------------- main GEMM: fp16 2-term, K32, 2-stage, 1 sync/iter ----------
// regions per stage: Ah 10240 | Al 10240 | Bh 10240
#define RSTG 10240
#define MMSTG (3*RSTG)          // 30720
#define MM_SMEM (2*MMSTG)       // 61440
#define NKT (HH/32)             // 32

__global__ void __launch_bounds__(256, 2) mm_kernel(int mode, float* __restrict__ Cext,
                                                    const float* __restrict__ ba,
                                                    const float* __restrict__ bb)
{
    extern __shared__ __align__(16) __half smem_h[];

    if (mode == 0 && blockIdx.x == 32){
        ab_mma_body(smem_h, ba, bb);
        return;
    }

    const uint32_t sba = (uint32_t)__cvta_generic_to_shared(smem_h);
    const int tid = threadIdx.x;
    const int wid = tid >> 5, lid = tid & 31;
    const int g = lid >> 2, tg = lid & 3;
    const int wm = wid & 1, wn = wid >> 1;

    const int m0 = blockIdx.y * 128;
    const int n0 = blockIdx.x * 128;
    const int wrow = (mode ? 4096 : 0) + n0;
    const __half* Ah = mode ? g_ahi : g_xhi;
    const __half* Al = mode ? g_alo : g_xlo;

    float acc[4][4][4];
    #pragma unroll
    for (int a=0;a<4;a++)
        #pragma unroll
        for (int b=0;b<4;b++)
            #pragma unroll
            for (int c=0;c<4;c++) acc[a][b][c] = 0.f;

    const uint32_t laneA = (uint32_t)((lid & 15)*80 + (lid >> 4)*16);
    const uint32_t laneB = (uint32_t)((((lid >> 4) & 1)*8 + (lid & 7))*80 + ((lid >> 3) & 1)*16);

    const int ch0row = tid >> 1;               // chunk tid: row=tid>>1? careful below
    // per stage: 3 regions x 512 chunks (128 rows x 4 x16B); thread covers chunk tid and tid+256
    auto load_stage = [&](int kt){
        const uint32_t sb2 = sba + (uint32_t)((kt & 1) * MMSTG);
        const int k0 = kt * 32;
        #pragma unroll
        for (int half = 0; half < 2; ++half){
            const int ch = tid + 256*half;      // 0..511
            const int row = ch >> 2, c16 = ch & 3;
            const uint32_t d = (uint32_t)(row*80 + c16*16);
            const size_t ka = (size_t)k0 + c16*8;
            const size_t aoff = (size_t)(m0 + row)*HH + ka;
            const size_t boff = (size_t)(wrow + row)*HH + ka;
            cp16(sb2 + d,           Ah    + aoff);
            cp16(sb2 + RSTG + d,    Al    + aoff);
            cp16(sb2 + 2*RSTG + d,  g_whi + boff);
        }
        asm volatile("cp.async.commit_group;" ::: "memory");
    };
    (void)ch0row;

    load_stage(0);

    for (int kt = 0; kt < NKT; ++kt){
        asm volatile("cp.async.wait_group 0;" ::: "memory");
        __syncthreads();
        if (kt + 1 < NKT) load_stage(kt + 1);

        const uint32_t stgb = sba + (uint32_t)((kt & 1) * MMSTG);
        const uint32_t aAh = stgb +           laneA + (uint32_t)(wm*64)*80;
        const uint32_t aAl = stgb + RSTG    + laneA + (uint32_t)(wm*64)*80;
        const uint32_t aBh = stgb + 2*RSTG  + laneB + (uint32_t)(wn*32)*80;

        uint32_t bh[2][4][2];
        #pragma unroll
        for (int ks = 0; ks < 2; ++ks){
            const uint32_t kb = (uint32_t)(ks*32);
            uint32_t r[4];
            ldsm4(r, aBh + kb);
            bh[ks][0][0]=r[0]; bh[ks][0][1]=r[1]; bh[ks][1][0]=r[2]; bh[ks][1][1]=r[3];
            ldsm4(r, aBh + kb + 16*80);
            bh[ks][2][0]=r[0]; bh[ks][2][1]=r[1]; bh[ks][3][0]=r[2]; bh[ks][3][1]=r[3];
        }

        #pragma unroll
        for (int ks = 0; ks < 2; ++ks){
            const uint32_t kb = (uint32_t)(ks*32);
            #pragma unroll
            for (int mt = 0; mt < 4; ++mt){
                uint32_t af[4];
                ldsm4(af, aAh + kb + (uint32_t)(mt*16)*80);
                #pragma unroll
                for (int nt = 0; nt < 4; ++nt)
                    mma16816(acc[mt][nt], af, bh[ks][nt]);
                ldsm4(af, aAl + kb + (uint32_t)(mt*16)*80);
                #pragma unroll
                for (int nt = 0; nt < 4; ++nt)
                    mma16816(acc[mt][nt], af, bh[ks][nt]);
            }
        }
    }

    float* dst; int epi = 0; int colb;
    if (mode == 0){
        const int mat = n0 >> 10;
        colb = n0 & 1023;
        switch (mat){
            case 0: dst = g_q; break;
            case 1: dst = g_k; break;
            case 2: dst = g_v; epi = 1; break;
            default: dst = g_g; epi = 1; break;
        }
    } else { dst = Cext; colb = n0; }

    #pragma unroll
    for (int mt = 0; mt < 4; ++mt){
        const int r = m0 + wm*64 + mt*16 + g;
        #pragma unroll
        for (int nt = 0; nt < 4; ++nt){
            const int cidx = colb + wn*32 + nt*8 + 2*tg;
            float v0 = acc[mt][nt][0], v1 = acc[mt][nt][1];
            float v2 = acc[mt][nt][2], v3 = acc[mt][nt][3];
            if (epi){
                v0 *= sigmoidf_(v0); v1 *= sigmoidf_(v1);
                v2 *= sigmoidf_(v2); v3 *= sigmoidf_(v3);
            }
            *reinterpret_cast<float2*>(dst + (size_t)r*HH + cidx)     = make_float2(v0, v1);
            *reinterpret_cast<float2*>(dst + (size_t)(r+8)*HH + cidx) = make_float2(v2, v3);
        }
    }
}

// ---------------- in-smem per-row L2 normalize helper -------------------------
__device__ __forceinline__ void l2norm_smem(float* buf, int w, int l)
{
    const int row = w*4 + (l >> 3);
    const int col = (l & 7) * 8;
    float* p = buf + row*HD + col;
    const float4 a0 = *reinterpret_cast<const float4*>(p);
    const float4 a1 = *reinterpret_cast<const float4*>(p + 4);
    float ss = a0.x*a0.x + a0.y*a0.y + a0.z*a0.z + a0.w*a0.w
             + a1.x*a1.x + a1.y*a1.y + a1.z*a1.z + a1.w*a1.w;
    ss += __shfl_xor_sync(0xffffffffu, ss, 1);
    ss += __shfl_xor_sync(0xffffffffu, ss, 2);
    ss += __shfl_xor_sync(0xffffffffu, ss, 4);
    const float inv = 1.f / fmaxf(sqrtf(ss), 1e-12f);
    *reinterpret_cast<float4*>(p)     = make_float4(a0.x*inv, a0.y*inv, a0.z*inv, a0.w*inv);
    *reinterpret_cast<float4*>(p + 4) = make_float4(a1.x*inv, a1.y*inv, a1.z*inv, a1.w*inv);
}

// ---------------- recurrence pass 1 (fused k-normalization) -------------------
__global__ void __launch_bounds__(512) pass1_kernel()
{
    const int c = blockIdx.x, bh = blockIdx.y;
    const int b = bh >> 4, h = bh & 15;
    const int tid = threadIdx.x;
    const int w = tid >> 5, l = tid & 31;
    __shared__ __align__(16) float ks[CHUNK*HD];
    __shared__ __align__(16) float vs[CHUNK*HD];
    __shared__ float aa[CHUNK], bbs[CHUNK];

    const int row0 = b*SS + c*CHUNK;
    for (int idx = tid; idx < CHUNK*16; idx += 512){
        const int t = idx >> 4, c4 = (idx & 15) * 4;
        const size_t go = (size_t)(row0 + t)*HH + h*HD + c4;
        *reinterpret_cast<float4*>(&ks[t*HD + c4]) = *reinterpret_cast<const float4*>(&g_k[go]);
        *reinterpret_cast<float4*>(&vs[t*HD + c4]) = *reinterpret_cast<const float4*>(&g_v[go]);
    }
    if (tid < CHUNK){
        aa[tid]  = g_alpha[(row0 + tid)*NH + h];
        bbs[tid] = g_beta [(row0 + tid)*NH + h];
    }
    __syncthreads();
    l2norm_smem(ks, w, l);
    __syncthreads();

    float M[4][2], Cc[4][2];
    #pragma unroll
    for (int r=0;r<4;r++){ M[r][0]=1.f; M[r][1]=1.f; Cc[r][0]=0.f; Cc[r][1]=0.f; }

    #pragma unroll 2
    for (int t=0;t<CHUNK;++t){
        const float a = aa[t], bt = bbs[t], abp = a*bt;
        const float kj0 = ks[t*HD + l], kj1 = ks[t*HD + l + 32];
        #pragma unroll
        for (int r=0;r<4;r++){
            const int i = w*4 + r;
            const float ki = ks[t*HD + i];
            const float bvi = bt * vs[t*HD + i];
            const float abki = abp * ki;
            const float m0 = fmaf(-abki, kj0, a);
            const float m1 = fmaf(-abki, kj1, a);
            M[r][0] *= m0;  M[r][1] *= m1;
            Cc[r][0] = fmaf(m0, Cc[r][0], bvi*kj0);
            Cc[r][1] = fmaf(m1, Cc[r][1], bvi*kj1);
        }
    }
    const size_t ob = ((size_t)bh*NCHUNK + c) * SE;
    #pragma unroll
    for (int r=0;r<4;r++){
        const int i = w*4 + r;
        g_M [ob + i*HD + l]      = M[r][0];
        g_M [ob + i*HD + l + 32] = M[r][1];
        g_Cc[ob + i*HD + l]      = Cc[r][0];
        g_Cc[ob + i*HD + l + 32] = Cc[r][1];
    }
}

// ---------------- serial scan over chunks (128 blocks, 4 chains/thread) ------
__global__ void __launch_bounds__(512) scan_kernel()
{
    const int bh = blockIdx.x >> 1, part = blockIdx.x & 1;
    const size_t base = (size_t)bh * NCHUNK * SE + part*2048 + threadIdx.x;
    float s[4];
    #pragma unroll
    for (int u=0;u<4;u++) s[u] = 0.f;
    for (int c=0;c<NCHUNK;++c){
        const size_t cb = base + (size_t)c*SE;
        #pragma unroll
        for (int u=0;u<4;u++){
            const size_t idx = cb + (size_t)u*512;
            g_S0[idx] = s[u];
            s[u] = fmaf(g_M[idx], s[u], g_Cc[idx]);
        }
    }
}

// ---------------- recurrence pass 2 (fused k,q normalization) -----------------
#define P2_SMEM (4*CHUNK*HD*4 + 2*CHUNK*4)   // 66048 B
__global__ void __launch_bounds__(512) pass2_kernel()
{
    const int c = blockIdx.x, bh = blockIdx.y;
    const int b = bh >> 4, h = bh & 15;
    const int tid = threadIdx.x;
    const int w = tid >> 5, l = tid & 31;
    extern __shared__ __align__(16) float p2s[];
    float* ks  = p2s;
    float* vs  = p2s + CHUNK*HD;
    float* qs  = p2s + 2*CHUNK*HD;
    float* outs= p2s + 3*CHUNK*HD;
    float* aa  = p2s + 4*CHUNK*HD;
    float* bbs = aa + CHUNK;

    const int row0 = b*SS + c*CHUNK;
    for (int idx = tid; idx < CHUNK*16; idx += 512){
        const int t = idx >> 4, c4 = (idx & 15) * 4;
        const size_t go = (size_t)(row0 + t)*HH + h*HD + c4;
        *reinterpret_cast<float4*>(&ks[t*HD + c4]) = *reinterpret_cast<const float4*>(&g_k[go]);
        *reinterpret_cast<float4*>(&vs[t*HD + c4]) = *reinterpret_cast<const float4*>(&g_v[go]);
        *reinterpret_cast<float4*>(&qs[t*HD + c4]) = *reinterpret_cast<const float4*>(&g_q[go]);
    }
    if (tid < CHUNK){
        aa[tid]  = g_alpha[(row0 + tid)*NH + h];
        bbs[tid] = g_beta [(row0 + tid)*NH + h];
    }

    float st[4][2];
    const size_t sbg = ((size_t)bh*NCHUNK + c) * SE;
    #pragma unroll
    for (int r=0;r<4;r++){
        const int i = w*4 + r;
        st[r][0] = g_S0[sbg + i*HD + l];
        st[r][1] = g_S0[sbg + i*HD + l + 32];
    }
    __syncthreads();
    l2norm_smem(ks, w, l);
    l2norm_smem(qs, w, l);
    __syncthreads();

    #pragma unroll 2
    for (int t=0;t<CHUNK;++t){
        const float a = aa[t], bt = bbs[t], abp = a*bt;
        const float kj0 = ks[t*HD + l], kj1 = ks[t*HD + l + 32];
        const float qj0 = qs[t*HD + l], qj1 = qs[t*HD + l + 32];
        float p[4];
        #pragma unroll
        for (int r=0;r<4;r++){
            const int i = w*4 + r;
            const float ki = ks[t*HD + i];
            const float bvi = bt * vs[t*HD + i];
            const float abki = abp * ki;
            const float m0 = fmaf(-abki, kj0, a);
            const float m1 = fmaf(-abki, kj1, a);
            st[r][0] = fmaf(m0, st[r][0], bvi*kj0);
            st[r][1] = fmaf(m1, st[r][1], bvi*kj1);
            p[r] = fmaf(st[r][0], qj0, st[r][1]*qj1);
        }
        #pragma unroll
        for (int o=16;o;o>>=1){
            p[0] += __shfl_xor_sync(0xffffffffu, p[0], o);
            p[1] += __shfl_xor_sync(0xffffffffu, p[1], o);
            p[2] += __shfl_xor_sync(0xffffffffu, p[2], o);
            p[3] += __shfl_xor_sync(0xffffffffu, p[3], o);
        }
        if (l < 4) outs[t*HD + w*4 + l] = p[l];
    }
    __syncthreads();
    for (int idx = tid; idx < CHUNK*16; idx += 512){
        const int t = idx >> 4, c4 = (idx & 15) * 4;
        const size_t go = (size_t)(row0 + t)*HH + h*HD + c4;
        *reinterpret_cast<float4*>(&g_attn[go]) = *reinterpret_cast<const float4*>(&outs[t*HD + c4]);
    }
}

// ---------------- LayerNorm + SiLU-gate + fp16 split (fused) -----------------
__global__ void __launch_bounds__(256) ln_gate_kernel(
    const float* __restrict__ lng, const float* __restrict__ lnb)
{
    const int r = blockIdx.x, tid = threadIdx.x;
    __shared__ float xs[HH];
    __shared__ float red[8];
    const float* row = g_attn + (size_t)r*HH;
    float s = 0.f;
    for (int i=tid;i<HH;i+=256){ float v = row[i]; xs[i] = v; s += v; }
    #pragma unroll
    for (int o=16;o;o>>=1) s += __shfl_xor_sync(0xffffffffu, s, o);
    if ((tid & 31) == 0) red[tid>>5] = s;
    __syncthreads();
    float tot = red[0]+red[1]+red[2]+red[3]+red[4]+red[5]+red[6]+red[7];
    const float mu = tot * (1.f/HH);
    __syncthreads();
    float vsum = 0.f;
    for (int i=tid;i<HH;i+=256){ float d = xs[i]-mu; vsum = fmaf(d,d,vsum); }
    #pragma unroll
    for (int o=16;o;o>>=1) vsum += __shfl_xor_sync(0xffffffffu, vsum, o);
    if ((tid & 31) == 0) red[tid>>5] = vsum;
    __syncthreads();
    float vtot = red[0]+red[1]+red[2]+red[3]+red[4]+red[5]+red[6]+red[7];
    const float rstd = rsqrtf(vtot*(1.f/HH) + 1e-5f);
    for (int i=tid*4;i<HH;i+=256*4){
        float4 gv = *reinterpret_cast<const float4*>(g_g + (size_t)r*HH + i);
        float4 yv;
        yv.x = ((xs[i+0]-mu)*rstd*lng[i+0] + lnb[i+0]) * gv.x;
        yv.y = ((xs[i+1]-mu)*rstd*lng[i+1] + lnb[i+1]) * gv.y;
        yv.z = ((xs[i+2]-mu)*rstd*lng[i+2] + lnb[i+2]) * gv.z;
        yv.w = ((xs[i+3]-mu)*rstd*lng[i+3] + lnb[i+3]) * gv.w;
        split4h(yv, g_ahi + (size_t)r*HH + i, g_alo + (size_t)r*HH + i);
    }
}

// ---------------- launch -----------------------------------------------------
extern "C" void kernel_launch(void* const* d_in, const int* in_sizes, int n_in,
                              void* d_out, int out_size)
{
    const float* x   = (const float*)d_in[0];
    const float* Wq  = (const float*)d_in[1];
    const float* Wk  = (const float*)d_in[2];
    const float* Wv  = (const float*)d_in[3];
    const float* Wa  = (const float*)d_in[4];
    const float* ba  = (const float*)d_in[5];
    const float* Wb  = (const float*)d_in[6];
    const float* bb  = (const float*)d_in[7];
    const float* Wg  = (const float*)d_in[8];
    const float* Wo  = (const float*)d_in[9];
    const float* lng = (const float*)d_in[10];
    const float* lnb = (const float*)d_in[11];
    float* out = (float*)d_out;

    cudaFuncSetAttribute(mm_kernel, cudaFuncAttributeMaxDynamicSharedMemorySize, MM_SMEM);
    cudaFuncSetAttribute(pass2_kernel, cudaFuncAttributeMaxDynamicSharedMemorySize, P2_SMEM);

    cvt_all_kernel<<<(CVT_TOT+255)/256, 256>>>(x, Wq, Wk, Wv, Wg, Wo, Wa, Wb);
    mm_kernel<<<dim3(33, 64), 256, MM_SMEM>>>(0, nullptr, ba, bb);  // QKVG + alpha/beta
    pass1_kernel<<<dim3(NCHUNK, BHDIM), 512>>>();
    scan_kernel<<<2*BHDIM, 512>>>();
    pass2_kernel<<<dim3(NCHUNK, BHDIM), 512, P2_SMEM>>>();
    ln_gate_kernel<<<NROWS, 256>>>(lng, lnb);
    mm_kernel<<<dim3(8, 64), 256, MM_SMEM>>>(1, out, nullptr, nullptr);
}

// round 13
// speedup vs baseline: 1.2547x; 1.0155x over previous
#include <cuda_runtime.h>
#include <cuda_fp16.h>
#include <cstdint>

// Problem constants
#define BB 4
#define SS 2048
#define HH 1024
#define NH 16
#define HD 64
#define NROWS (BB*SS)          // 8192
#define CHUNK 64
#define NCHUNK (SS/CHUNK)      // 32
#define BHDIM (BB*NH)          // 64
#define SE (HD*HD)             // 4096

// ---------------- scratch (static __device__, allocation-free) ----------------
__device__ __align__(16) float g_q[(size_t)NROWS*HH];
__device__ __align__(16) float g_k[(size_t)NROWS*HH];
__device__ __align__(16) float g_v[(size_t)NROWS*HH];
__device__ __align__(16) float g_g[(size_t)NROWS*HH];
__device__ __align__(16) float g_attn[(size_t)NROWS*HH];
__device__ float g_alpha[NROWS*NH];
__device__ float g_beta[NROWS*NH];
__device__ __align__(16) float g_M [(size_t)BHDIM*NCHUNK*SE];
__device__ __align__(16) float g_Cc[(size_t)BHDIM*NCHUNK*SE];
__device__ __align__(16) float g_S0[(size_t)BHDIM*NCHUNK*SE];

// fp16 split buffers (A side: hi+lo; B side: hi only)
__device__ __align__(16) __half g_xhi[(size_t)NROWS*HH];
__device__ __align__(16) __half g_xlo[(size_t)NROWS*HH];
__device__ __align__(16) __half g_whi[(size_t)5*HH*HH];
__device__ __align__(16) __half g_ahi[(size_t)NROWS*HH];
__device__ __align__(16) __half g_alo[(size_t)NROWS*HH];
__device__ __align__(16) __half g_abhi[2*NH*HH];

__device__ __forceinline__ float sigmoidf_(float z){ return 1.f/(1.f+expf(-z)); }

__device__ __forceinline__ void split4h(float4 v, __half* hi, __half* lo){
    float f[4] = {v.x, v.y, v.z, v.w};
    __half h[4], l[4];
    #pragma unroll
    for (int j=0;j<4;j++){
        h[j] = __float2half_rn(f[j]);
        l[j] = __float2half_rn(f[j] - __half2float(h[j]));
    }
    reinterpret_cast<__half2*>(hi)[0] = __halves2half2(h[0], h[1]);
    reinterpret_cast<__half2*>(hi)[1] = __halves2half2(h[2], h[3]);
    reinterpret_cast<__half2*>(lo)[0] = __halves2half2(l[0], l[1]);
    reinterpret_cast<__half2*>(lo)[1] = __halves2half2(l[2], l[3]);
}

__device__ __forceinline__ void cvt4h(float4 v, __half* hi){
    reinterpret_cast<__half2*>(hi)[0] = __halves2half2(__float2half_rn(v.x), __float2half_rn(v.y));
    reinterpret_cast<__half2*>(hi)[1] = __halves2half2(__float2half_rn(v.z), __float2half_rn(v.w));
}

// ---------------- fused fp32 -> fp16 conversion (x split | 5 W hi | Wab hi) --
#define XN4 ((NROWS*HH)/4)      // 2097152
#define WN4 ((HH*HH)/4)         // 262144
#define QN4 ((NH*HH)/4)         // 4096
#define CVT_TOT (XN4 + 5*WN4 + 2*QN4)

__global__ void __launch_bounds__(256) cvt_all_kernel(
    const float* __restrict__ x,
    const float* __restrict__ W0, const float* __restrict__ W1,
    const float* __restrict__ W2, const float* __restrict__ W3,
    const float* __restrict__ W4,
    const float* __restrict__ Wa, const float* __restrict__ Wb)
{
    const int i = blockIdx.x*256 + threadIdx.x;
    if (i >= CVT_TOT) return;
    if (i < XN4){
        split4h(reinterpret_cast<const float4*>(x)[i], g_xhi + 4*(size_t)i, g_xlo + 4*(size_t)i);
    } else if (i < XN4 + 5*WN4){
        const int j5 = i - XN4;
        const int mat = j5 / WN4, j = j5 - mat*WN4;
        const float* src;
        switch (mat){
            case 0: src = W0; break; case 1: src = W1; break;
            case 2: src = W2; break; case 3: src = W3; break;
            default: src = W4; break;
        }
        cvt4h(reinterpret_cast<const float4*>(src)[j], g_whi + (size_t)mat*HH*HH + 4*(size_t)j);
    } else {
        const int j = i - XN4 - 5*WN4;
        float4 v = (j < QN4) ? reinterpret_cast<const float4*>(Wa)[j]
                             : reinterpret_cast<const float4*>(Wb)[j-QN4];
        cvt4h(v, g_abhi + 4*(size_t)j);
    }
}

// ---------------- common mma/ldsm/cp helpers ---------------------------------
__device__ __forceinline__ void cp16(uint32_t smem, const void* gptr){
    const unsigned long long g = (unsigned long long)__cvta_generic_to_global(gptr);
    asm volatile("cp.async.cg.shared.global [%0], [%1], 16;" :: "r"(smem), "l"(g) : "memory");
}

__device__ __forceinline__ void mma16816(float* c, const uint32_t* a, const uint32_t* b){
    asm volatile("mma.sync.aligned.m16n8k16.row.col.f32.f16.f16.f32 "
        "{%0,%1,%2,%3}, {%4,%5,%6,%7}, {%8,%9}, {%0,%1,%2,%3};"
        : "+f"(c[0]), "+f"(c[1]), "+f"(c[2]), "+f"(c[3])
        : "r"(a[0]), "r"(a[1]), "r"(a[2]), "r"(a[3]), "r"(b[0]), "r"(b[1]));
}

__device__ __forceinline__ void ldsm4(uint32_t* r, uint32_t addr){
    asm volatile("ldmatrix.sync.aligned.m8n8.x4.shared.b16 {%0,%1,%2,%3}, [%4];"
        : "=r"(r[0]), "=r"(r[1]), "=r"(r[2]), "=r"(r[3]) : "r"(addr));
}

// ---------------- alpha/beta GEMM body (runs inside mm0 grid) ----------------
// regions: Ah 10240 | Al 10240 | Bh 2560 per stage (2-stage inside 92KB alloc)
#define ABSTG 23040
#define ABNKT (HH/32)

__device__ void ab_mma_body(__half* smem_ab,
                            const float* __restrict__ ba, const float* __restrict__ bb)
{
    const uint32_t sba = (uint32_t)__cvta_generic_to_shared(smem_ab);
    const int tid = threadIdx.x;
    const int wid = tid >> 5, lid = tid & 31;
    const int g = lid >> 2, tg = lid & 3;
    const int m0 = blockIdx.y * 128;

    float acc[4][4];
    #pragma unroll
    for (int a=0;a<4;a++)
        #pragma unroll
        for (int b=0;b<4;b++) acc[a][b] = 0.f;

    const uint32_t laneA = (uint32_t)((lid & 15)*80 + (lid >> 4)*16);
    const uint32_t laneB = (uint32_t)((((lid >> 4) & 1)*8 + (lid & 7))*80 + ((lid >> 3) & 1)*16);

    auto load_stage = [&](int kt){
        const uint32_t sb2 = sba + (uint32_t)((kt & 1) * ABSTG);
        const int k0 = kt * 32;
        for (int idx = tid; idx < 1152; idx += 256){
            uint32_t dst; const __half* src; size_t off;
            if (idx < 512){
                const int r = idx >> 2, c = idx & 3;
                dst = sb2 + (uint32_t)(r*80 + c*16);
                src = g_xhi; off = (size_t)(m0 + r)*HH + k0 + c*8;
            } else if (idx < 1024){
                const int q = idx - 512, r = q >> 2, c = q & 3;
                dst = sb2 + 10240 + (uint32_t)(r*80 + c*16);
                src = g_xlo; off = (size_t)(m0 + r)*HH + k0 + c*8;
            } else {
                const int q = idx - 1024, r = q >> 2, c = q & 3;
                dst = sb2 + 20480 + (uint32_t)(r*80 + c*16);
                src = g_abhi; off = (size_t)r*HH + k0 + c*8;
            }
            cp16(dst, src + off);
        }
        asm volatile("cp.async.commit_group;" ::: "memory");
    };

    load_stage(0);

    for (int kt = 0; kt < ABNKT; ++kt){
        if (kt + 1 < ABNKT) load_stage(kt + 1);
        if (kt + 1 < ABNKT) asm volatile("cp.async.wait_group 1;" ::: "memory");
        else                asm volatile("cp.async.wait_group 0;" ::: "memory");
        __syncthreads();

        const uint32_t base = sba + (uint32_t)((kt & 1) * ABSTG);
        const uint32_t aAh = base +         laneA + (uint32_t)(wid*16)*80;
        const uint32_t aAl = base + 10240 + laneA + (uint32_t)(wid*16)*80;
        const uint32_t aBh = base + 20480 + laneB;

        #pragma unroll
        for (int ks = 0; ks < 2; ++ks){
            const uint32_t kb = (uint32_t)(ks*32);
            uint32_t bh[4][2];
            {
                uint32_t r[4];
                ldsm4(r, aBh + kb);
                bh[0][0]=r[0]; bh[0][1]=r[1]; bh[1][0]=r[2]; bh[1][1]=r[3];
                ldsm4(r, aBh + kb + 16*80);
                bh[2][0]=r[0]; bh[2][1]=r[1]; bh[3][0]=r[2]; bh[3][1]=r[3];
            }
            uint32_t af[4];
            ldsm4(af, aAh + kb);
            #pragma unroll
            for (int nt = 0; nt < 4; ++nt)
                mma16816(acc[nt], af, bh[nt]);
            ldsm4(af, aAl + kb);
            #pragma unroll
            for (int nt = 0; nt < 4; ++nt)
                mma16816(acc[nt], af, bh[nt]);
        }
        __syncthreads();
    }

    const int r0 = m0 + wid*16 + g;
    #pragma unroll
    for (int nt = 0; nt < 4; ++nt){
        const int n = nt*8 + 2*tg;
        #pragma unroll
        for (int e = 0; e < 2; ++e){
            const int nn = n + e;
            const float bias = (nn < NH) ? ba[nn] : bb[nn - NH];
            float v0 = sigmoidf_(acc[nt][e]     + bias);
            float v1 = sigmoidf_(acc[nt][e + 2] + bias);
            if (nn < NH){
                g_alpha[r0*NH + nn]     = v0;
                g_alpha[(r0+8)*NH + nn] = v1;
            } else {
                g_beta[r0*NH + nn - NH]     = v0;
                g_beta[(r0+8)*NH + nn - NH] = v1;
            }
        }
    }
}

// ---------------- main GEMM: fp16 2-term, K32, 3-stage ring, wait 1 ----------
// regions per stage: Ah 10240 | Al 10240 | Bh 10240
#define RSTG 10240
#define MMSTG (3*RSTG)          // 30720
#define MM_SMEM (3*MMSTG)       // 92160  (3-stage)
#define NKT (HH/32)             // 32

__global__ void __launch_bounds__(256, 2) mm_kernel(int mode, float* __restrict__ Cext,
                                                    const float* __restrict__ ba,
                                                    const float* __restrict__ bb)
{
    extern __shared__ __align__(16) __half smem_h[];

    if (mode == 0 && blockIdx.x == 32){
        ab_mma_body(smem_h, ba, bb);
        return;
    }

    const uint32_t sba = (uint32_t)__cvta_generic_to_shared(smem_h);
    const int tid = threadIdx.x;
    const int wid = tid >> 5, lid = tid & 31;
    const int g = lid >> 2, tg = lid & 3;
    const int wm = wid & 1, wn = wid >> 1;

    const int m0 = blockIdx.y * 128;
    const int n0 = blockIdx.x * 128;
    const int wrow = (mode ? 4096 : 0) + n0;
    const __half* Ah = mode ? g_ahi : g_xhi;
    const __half* Al = mode ? g_alo : g_xlo;

    float acc[4][4][4];
    #pragma unroll
    for (int a=0;a<4;a++)
        #pragma unroll
        for (int b=0;b<4;b++)
            #pragma unroll
            for (int c=0;c<4;c++) acc[a][b][c] = 0.f;

    const uint32_t laneA = (uint32_t)((lid & 15)*80 + (lid >> 4)*16);
    const uint32_t laneB = (uint32_t)((((lid >> 4) & 1)*8 + (lid & 7))*80 + ((lid >> 3) & 1)*16);

    // stage buffer index cycles 0,1,2
    auto load_stage = [&](int kt, int buf){
        const uint32_t sb2 = sba + (uint32_t)(buf * MMSTG);
        const int k0 = kt * 32;
        #pragma unroll
        for (int half = 0; half < 2; ++half){
            const int ch = tid + 256*half;      // 0..511
            const int row = ch >> 2, c16 = ch & 3;
            const uint32_t d = (uint32_t)(row*80 + c16*16);
            const size_t ka = (size_t)k0 + c16*8;
            const size_t aoff = (size_t)(m0 + row)*HH + ka;
            const size_t boff = (size_t)(wrow + row)*HH + ka;
            cp16(sb2 + d,           Ah    + aoff);
            cp16(sb2 + RSTG + d,    Al    + aoff);
            cp16(sb2 + 2*RSTG + d,  g_whi + boff);
        }
    };

    load_stage(0, 0); asm volatile("cp.async.commit_group;" ::: "memory");
    load_stage(1, 1); asm volatile("cp.async.commit_group;" ::: "memory");

    int buf = 0;
    for (int kt = 0; kt < NKT; ++kt){
        asm volatile("cp.async.wait_group 1;" ::: "memory");   // stage kt done; kt+1 may fly
        __syncthreads();
        // issue stage kt+2 into buffer (buf+2)%3 — its last reader finished at iter kt-1,
        // proven by this sync. Always commit to keep group accounting exact.
        if (kt + 2 < NKT) load_stage(kt + 2, (buf + 2 >= 3) ? buf - 1 : buf + 2);
        asm volatile("cp.async.commit_group;" ::: "memory");

        const uint32_t stgb = sba + (uint32_t)(buf * MMSTG);
        const uint32_t aAh = stgb +           laneA + (uint32_t)(wm*64)*80;
        const uint32_t aAl = stgb + RSTG    + laneA + (uint32_t)(wm*64)*80;
        const uint32_t aBh = stgb + 2*RSTG  + laneB + (uint32_t)(wn*32)*80;

        uint32_t bh[2][4][2];
        #pragma unroll
        for (int ks = 0; ks < 2; ++ks){
            const uint32_t kb = (uint32_t)(ks*32);
            uint32_t r[4];
            ldsm4(r, aBh + kb);
            bh[ks][0][0]=r[0]; bh[ks][0][1]=r[1]; bh[ks][1][0]=r[2]; bh[ks][1][1]=r[3];
            ldsm4(r, aBh + kb + 16*80);
            bh[ks][2][0]=r[0]; bh[ks][2][1]=r[1]; bh[ks][3][0]=r[2]; bh[ks][3][1]=r[3];
        }

        #pragma unroll
        for (int ks = 0; ks < 2; ++ks){
            const uint32_t kb = (uint32_t)(ks*32);
            #pragma unroll
            for (int mt = 0; mt < 4; ++mt){
                uint32_t af[4];
                ldsm4(af, aAh + kb + (uint32_t)(mt*16)*80);
                #pragma unroll
                for (int nt = 0; nt < 4; ++nt)
                    mma16816(acc[mt][nt], af, bh[ks][nt]);
                ldsm4(af, aAl + kb + (uint32_t)(mt*16)*80);
                #pragma unroll
                for (int nt = 0; nt < 4; ++nt)
                    mma16816(acc[mt][nt], af, bh[ks][nt]);
            }
        }
        buf = (buf + 1 >= 3) ? 0 : buf + 1;
    }

    float* dst; int epi = 0; int colb;
    if (mode == 0){
        const int mat = n0 >> 10;
        colb = n0 & 1023;
        switch (mat){
            case 0: dst = g_q; break;
            case 1: dst = g_k; break;
            case 2: dst = g_v; epi = 1; break;
            default: dst = g_g; epi = 1; break;
        }
    } else { dst = Cext; colb = n0; }

    #pragma unroll
    for (int mt = 0; mt < 4; ++mt){
        const int r = m0 + wm*64 + mt*16 + g;
        #pragma unroll
        for (int nt = 0; nt < 4; ++nt){
            const int cidx = colb + wn*32 + nt*8 + 2*tg;
            float v0 = acc[mt][nt][0], v1 = acc[mt][nt][1];
            float v2 = acc[mt][nt][2], v3 = acc[mt][nt][3];
            if (epi){
                v0 *= sigmoidf_(v0); v1 *= sigmoidf_(v1);
                v2 *= sigmoidf_(v2); v3 *= sigmoidf_(v3);
            }
            *reinterpret_cast<float2*>(dst + (size_t)r*HH + cidx)     = make_float2(v0, v1);
            *reinterpret_cast<float2*>(dst + (size_t)(r+8)*HH + cidx) = make_float2(v2, v3);
        }
    }
}

// ---------------- in-smem per-row L2 normalize helper -------------------------
__device__ __forceinline__ void l2norm_smem(float* buf, int w, int l)
{
    const int row = w*4 + (l >> 3);
    const int col = (l & 7) * 8;
    float* p = buf + row*HD + col;
    const float4 a0 = *reinterpret_cast<const float4*>(p);
    const float4 a1 = *reinterpret_cast<const float4*>(p + 4);
    float ss = a0.x*a0.x + a0.y*a0.y + a0.z*a0.z + a0.w*a0.w
             + a1.x*a1.x + a1.y*a1.y + a1.z*a1.z + a1.w*a1.w;
    ss += __shfl_xor_sync(0xffffffffu, ss, 1);
    ss += __shfl_xor_sync(0xffffffffu, ss, 2);
    ss += __shfl_xor_sync(0xffffffffu, ss, 4);
    const float inv = 1.f / fmaxf(sqrtf(ss), 1e-12f);
    *reinterpret_cast<float4*>(p)     = make_float4(a0.x*inv, a0.y*inv, a0.z*inv, a0.w*inv);
    *reinterpret_cast<float4*>(p + 4) = make_float4(a1.x*inv, a1.y*inv, a1.z*inv, a1.w*inv);
}

// ---------------- recurrence pass 1 (fused k-normalization) -------------------
__global__ void __launch_bounds__(512) pass1_kernel()
{
    const int c = blockIdx.x, bh = blockIdx.y;
    const int b = bh >> 4, h = bh & 15;
    const int tid = threadIdx.x;
    const int w = tid >> 5, l = tid & 31;
    __shared__ __align__(16) float ks[CHUNK*HD];
    __shared__ __align__(16) float vs[CHUNK*HD];
    __shared__ float aa[CHUNK], bbs[CHUNK];

    const int row0 = b*SS + c*CHUNK;
    for (int idx = tid; idx < CHUNK*16; idx += 512){
        const int t = idx >> 4, c4 = (idx & 15) * 4;
        const size_t go = (size_t)(row0 + t)*HH + h*HD + c4;
        *reinterpret_cast<float4*>(&ks[t*HD + c4]) = *reinterpret_cast<const float4*>(&g_k[go]);
        *reinterpret_cast<float4*>(&vs[t*HD + c4]) = *reinterpret_cast<const float4*>(&g_v[go]);
    }
    if (tid < CHUNK){
        aa[tid]  = g_alpha[(row0 + tid)*NH + h];
        bbs[tid] = g_beta [(row0 + tid)*NH + h];
    }
    __syncthreads();
    l2norm_smem(ks, w, l);
    __syncthreads();

    float M[4][2], Cc[4][2];
    #pragma unroll
    for (int r=0;r<4;r++){ M[r][0]=1.f; M[r][1]=1.f; Cc[r][0]=0.f; Cc[r][1]=0.f; }

    #pragma unroll 2
    for (int t=0;t<CHUNK;++t){
        const float a = aa[t], bt = bbs[t], abp = a*bt;
        const float kj0 = ks[t*HD + l], kj1 = ks[t*HD + l + 32];
        #pragma unroll
        for (int r=0;r<4;r++){
            const int i = w*4 + r;
            const float ki = ks[t*HD + i];
            const float bvi = bt * vs[t*HD + i];
            const float abki = abp * ki;
            const float m0 = fmaf(-abki, kj0, a);
            const float m1 = fmaf(-abki, kj1, a);
            M[r][0] *= m0;  M[r][1] *= m1;
            Cc[r][0] = fmaf(m0, Cc[r][0], bvi*kj0);
            Cc[r][1] = fmaf(m1, Cc[r][1], bvi*kj1);
        }
    }
    const size_t ob = ((size_t)bh*NCHUNK + c) * SE;
    #pragma unroll
    for (int r=0;r<4;r++){
        const int i = w*4 + r;
        g_M [ob + i*HD + l]      = M[r][0];
        g_M [ob + i*HD + l + 32] = M[r][1];
        g_Cc[ob + i*HD + l]      = Cc[r][0];
        g_Cc[ob + i*HD + l + 32] = Cc[r][1];
    }
}

// ---------------- serial scan over chunks (256 blocks, 2 chains/thread) ------
__global__ void __launch_bounds__(512) scan_kernel()
{
    const int bh = blockIdx.x >> 2, part = blockIdx.x & 3;
    const size_t base = (size_t)bh * NCHUNK * SE + part*1024 + threadIdx.x;
    float s[2];
    s[0] = 0.f; s[1] = 0.f;
    for (int c=0;c<NCHUNK;++c){
        const size_t cb = base + (size_t)c*SE;
        #pragma unroll
        for (int u=0;u<2;u++){
            const size_t idx = cb + (size_t)u*512;
            g_S0[idx] = s[u];
            s[u] = fmaf(g_M[idx], s[u], g_Cc[idx]);
        }
    }
}

// ---------------- recurrence pass 2 (fused k,q normalization) -----------------
#define P2_SMEM (4*CHUNK*HD*4 + 2*CHUNK*4)   // 66048 B
__global__ void __launch_bounds__(512) pass2_kernel()
{
    const int c = blockIdx.x, bh = blockIdx.y;
    const int b = bh >> 4, h = bh & 15;
    const int tid = threadIdx.x;
    const int w = tid >> 5, l = tid & 31;
    extern __shared__ __align__(16) float p2s[];
    float* ks  = p2s;
    float* vs  = p2s + CHUNK*HD;
    float* qs  = p2s + 2*CHUNK*HD;
    float* outs= p2s + 3*CHUNK*HD;
    float* aa  = p2s + 4*CHUNK*HD;
    float* bbs = aa + CHUNK;

    const int row0 = b*SS + c*CHUNK;
    for (int idx = tid; idx < CHUNK*16; idx += 512){
        const int t = idx >> 4, c4 = (idx & 15) * 4;
        const size_t go = (size_t)(row0 + t)*HH + h*HD + c4;
        *reinterpret_cast<float4*>(&ks[t*HD + c4]) = *reinterpret_cast<const float4*>(&g_k[go]);
        *reinterpret_cast<float4*>(&vs[t*HD + c4]) = *reinterpret_cast<const float4*>(&g_v[go]);
        *reinterpret_cast<float4*>(&qs[t*HD + c4]) = *reinterpret_cast<const float4*>(&g_q[go]);
    }
    if (tid < CHUNK){
        aa[tid]  = g_alpha[(row0 + tid)*NH + h];
        bbs[tid] = g_beta [(row0 + tid)*NH + h];
    }

    float st[4][2];
    const size_t sbg = ((size_t)bh*NCHUNK + c) * SE;
    #pragma unroll
    for (int r=0;r<4;r++){
        const int i = w*4 + r;
        st[r][0] = g_S0[sbg + i*HD + l];
        st[r][1] = g_S0[sbg + i*HD + l + 32];
    }
    __syncthreads();
    l2norm_smem(ks, w, l);
    l2norm_smem(qs, w, l);
    __syncthreads();

    #pragma unroll 2
    for (int t=0;t<CHUNK;++t){
        const float a = aa[t], bt = bbs[t], abp = a*bt;
        const float kj0 = ks[t*HD + l], kj1 = ks[t*HD + l + 32];
        const float qj0 = qs[t*HD + l], qj1 = qs[t*HD + l + 32];
        float p[4];
        #pragma unroll
        for (int r=0;r<4;r++){
            const int i = w*4 + r;
            const float ki = ks[t*HD + i];
            const float bvi = bt * vs[t*HD + i];
            const float abki = abp * ki;
            const float m0 = fmaf(-abki, kj0, a);
            const float m1 = fmaf(-abki, kj1, a);
            st[r][0] = fmaf(m0, st[r][0], bvi*kj0);
            st[r][1] = fmaf(m1, st[r][1], bvi*kj1);
            p[r] = fmaf(st[r][0], qj0, st[r][1]*qj1);
        }
        #pragma unroll
        for (int o=16;o;o>>=1){
            p[0] += __shfl_xor_sync(0xffffffffu, p[0], o);
            p[1] += __shfl_xor_sync(0xffffffffu, p[1], o);
            p[2] += __shfl_xor_sync(0xffffffffu, p[2], o);
            p[3] += __shfl_xor_sync(0xffffffffu, p[3], o);
        }
        if (l < 4) outs[t*HD + w*4 + l] = p[l];
    }
    __syncthreads();
    for (int idx = tid; idx < CHUNK*16; idx += 512){
        const int t = idx >> 4, c4 = (idx & 15) * 4;
        const size_t go = (size_t)(row0 + t)*HH + h*HD + c4;
        *reinterpret_cast<float4*>(&g_attn[go]) = *reinterpret_cast<const float4*>(&outs[t*HD + c4]);
    }
}

// ---------------- LayerNorm + SiLU-gate + fp16 split (fused) -----------------
__global__ void __launch_bounds__(256) ln_gate_kernel(
    const float* __restrict__ lng, const float* __restrict__ lnb)
{
    const int r = blockIdx.x, tid = threadIdx.x;
    __shared__ float xs[HH];
    __shared__ float red[8];
    const float* row = g_attn + (size_t)r*HH;
    float s = 0.f;
    for (int i=tid;i<HH;i+=256){ float v = row[i]; xs[i] = v; s += v; }
    #pragma unroll
    for (int o=16;o;o>>=1) s += __shfl_xor_sync(0xffffffffu, s, o);
    if ((tid & 31) == 0) red[tid>>5] = s;
    __syncthreads();
    float tot = red[0]+red[1]+red[2]+red[3]+red[4]+red[5]+red[6]+red[7];
    const float mu = tot * (1.f/HH);
    __syncthreads();
    float vsum = 0.f;
    for (int i=tid;i<HH;i+=256){ float d = xs[i]-mu; vsum = fmaf(d,d,vsum); }
    #pragma unroll
    for (int o=16;o;o>>=1) vsum += __shfl_xor_sync(0xffffffffu, vsum, o);
    if ((tid & 31) == 0) red[tid>>5] = vsum;
    __syncthreads();
    float vtot = red[0]+red[1]+red[2]+red[3]+red[4]+red[5]+red[6]+red[7];
    const float rstd = rsqrtf(vtot*(1.f/HH) + 1e-5f);
    for (int i=tid*4;i<HH;i+=256*4){
        float4 gv = *reinterpret_cast<const float4*>(g_g + (size_t)r*HH + i);
        float4 yv;
        yv.x = ((xs[i+0]-mu)*rstd*lng[i+0] + lnb[i+0]) * gv.x;
        yv.y = ((xs[i+1]-mu)*rstd*lng[i+1] + lnb[i+1]) * gv.y;
        yv.z = ((xs[i+2]-mu)*rstd*lng[i+2] + lnb[i+2]) * gv.z;
        yv.w = ((xs[i+3]-mu)*rstd*lng[i+3] + lnb[i+3]) * gv.w;
        split4h(yv, g_ahi + (size_t)r*HH + i, g_alo + (size_t)r*HH + i);
    }
}

// ---------------- launch -----------------------------------------------------
extern "C" void kernel_launch(void* const* d_in, const int* in_sizes, int n_in,
                              void* d_out, int out_size)
{
    const float* x   = (const float*)d_in[0];
    const float* Wq  = (const float*)d_in[1];
    const float* Wk  = (const float*)d_in[2];
    const float* Wv  = (const float*)d_in[3];
    const float* Wa  = (const float*)d_in[4];
    const float* ba  = (const float*)d_in[5];
    const float* Wb  = (const float*)d_in[6];
    const float* bb  = (const float*)d_in[7];
    const float* Wg  = (const float*)d_in[8];
    const float* Wo  = (const float*)d_in[9];
    const float* lng = (const float*)d_in[10];
    const float* lnb = (const float*)d_in[11];
    float* out = (float*)d_out;

    cudaFuncSetAttribute(mm_kernel, cudaFuncAttributeMaxDynamicSharedMemorySize, MM_SMEM);
    cudaFuncSetAttribute(pass2_kernel, cudaFuncAttributeMaxDynamicSharedMemorySize, P2_SMEM);

    cvt_all_kernel<<<(CVT_TOT+255)/256, 256>>>(x, Wq, Wk, Wv, Wg, Wo, Wa, Wb);
    mm_kernel<<<dim3(33, 64), 256, MM_SMEM>>>(0, nullptr, ba, bb);  // QKVG + alpha/beta
    pass1_kernel<<<dim3(NCHUNK, BHDIM), 512>>>();
    scan_kernel<<<4*BHDIM, 512>>>();
    pass2_kernel<<<dim3(NCHUNK, BHDIM), 512, P2_SMEM>>>();
    ln_gate_kernel<<<NROWS, 256>>>(lng, lnb);
    mm_kernel<<<dim3(8, 64), 256, MM_SMEM>>>(1, out, nullptr, nullptr);
}

// round 14
// speedup vs baseline: 1.2839x; 1.0233x over previous
#include <cuda_runtime.h>
#include <cuda_fp16.h>
#include <cstdint>

// Problem constants
#define BB 4
#define SS 2048
#define HH 1024
#define NH 16
#define HD 64
#define NROWS (BB*SS)          // 8192
#define CHUNK 64
#define NCHUNK (SS/CHUNK)      // 32
#define BHDIM (BB*NH)          // 64
#define SE (HD*HD)             // 4096

// ---------------- scratch (static __device__, allocation-free) ----------------
__device__ __align__(16) float g_q[(size_t)NROWS*HH];
__device__ __align__(16) float g_k[(size_t)NROWS*HH];
__device__ __align__(16) float g_v[(size_t)NROWS*HH];
__device__ __align__(16) float g_g[(size_t)NROWS*HH];
__device__ __align__(16) float g_attn[(size_t)NROWS*HH];
__device__ float g_alpha[NROWS*NH];
__device__ float g_beta[NROWS*NH];
__device__ __align__(16) float g_M [(size_t)BHDIM*NCHUNK*SE];
__device__ __align__(16) float g_Cc[(size_t)BHDIM*NCHUNK*SE];
__device__ __align__(16) float g_S0[(size_t)BHDIM*NCHUNK*SE];

// fp16 split buffers (A side: hi+lo; B side: hi only)
__device__ __align__(16) __half g_xhi[(size_t)NROWS*HH];
__device__ __align__(16) __half g_xlo[(size_t)NROWS*HH];
__device__ __align__(16) __half g_whi[(size_t)5*HH*HH];
__device__ __align__(16) __half g_ahi[(size_t)NROWS*HH];
__device__ __align__(16) __half g_alo[(size_t)NROWS*HH];
__device__ __align__(16) __half g_abhi[2*NH*HH];

__device__ __forceinline__ float sigmoidf_(float z){ return 1.f/(1.f+expf(-z)); }

__device__ __forceinline__ void split4h(float4 v, __half* hi, __half* lo){
    float f[4] = {v.x, v.y, v.z, v.w};
    __half h[4], l[4];
    #pragma unroll
    for (int j=0;j<4;j++){
        h[j] = __float2half_rn(f[j]);
        l[j] = __float2half_rn(f[j] - __half2float(h[j]));
    }
    reinterpret_cast<__half2*>(hi)[0] = __halves2half2(h[0], h[1]);
    reinterpret_cast<__half2*>(hi)[1] = __halves2half2(h[2], h[3]);
    reinterpret_cast<__half2*>(lo)[0] = __halves2half2(l[0], l[1]);
    reinterpret_cast<__half2*>(lo)[1] = __halves2half2(l[2], l[3]);
}

__device__ __forceinline__ void cvt4h(float4 v, __half* hi){
    reinterpret_cast<__half2*>(hi)[0] = __halves2half2(__float2half_rn(v.x), __float2half_rn(v.y));
    reinterpret_cast<__half2*>(hi)[1] = __halves2half2(__float2half_rn(v.z), __float2half_rn(v.w));
}

// ---------------- fused fp32 -> fp16 conversion (x split | 5 W hi | Wab hi) --
#define XN4 ((NROWS*HH)/4)      // 2097152
#define WN4 ((HH*HH)/4)         // 262144
#define QN4 ((NH*HH)/4)         // 4096
#define CVT_TOT (XN4 + 5*WN4 + 2*QN4)

__global__ void __launch_bounds__(256) cvt_all_kernel(
    const float* __restrict__ x,
    const float* __restrict__ W0, const float* __restrict__ W1,
    const float* __restrict__ W2, const float* __restrict__ W3,
    const float* __restrict__ W4,
    const float* __restrict__ Wa, const float* __restrict__ Wb)
{
    const int i = blockIdx.x*256 + threadIdx.x;
    if (i >= CVT_TOT) return;
    if (i < XN4){
        split4h(reinterpret_cast<const float4*>(x)[i], g_xhi + 4*(size_t)i, g_xlo + 4*(size_t)i);
    } else if (i < XN4 + 5*WN4){
        const int j5 = i - XN4;
        const int mat = j5 / WN4, j = j5 - mat*WN4;
        const float* src;
        switch (mat){
            case 0: src = W0; break; case 1: src = W1; break;
            case 2: src = W2; break; case 3: src = W3; break;
            default: src = W4; break;
        }
        cvt4h(reinterpret_cast<const float4*>(src)[j], g_whi + (size_t)mat*HH*HH + 4*(size_t)j);
    } else {
        const int j = i - XN4 - 5*WN4;
        float4 v = (j < QN4) ? reinterpret_cast<const float4*>(Wa)[j]
                             : reinterpret_cast<const float4*>(Wb)[j-QN4];
        cvt4h(v, g_abhi + 4*(size_t)j);
    }
}

// ---------------- common mma/ldsm/cp helpers ---------------------------------
__device__ __forceinline__ void cp16(uint32_t smem, const void* gptr){
    const unsigned long long g = (unsigned long long)__cvta_generic_to_global(gptr);
    asm volatile("cp.async.cg.shared.global [%0], [%1], 16;" :: "r"(smem), "l"(g) : "memory");
}

__device__ __forceinline__ void mma16816(float* c, const uint32_t* a, const uint32_t* b){
    asm volatile("mma.sync.aligned.m16n8k16.row.col.f32.f16.f16.f32 "
        "{%0,%1,%2,%3}, {%4,%5,%6,%7}, {%8,%9}, {%0,%1,%2,%3};"
        : "+f"(c[0]), "+f"(c[1]), "+f"(c[2]), "+f"(c[3])
        : "r"(a[0]), "r"(a[1]), "r"(a[2]), "r"(a[3]), "r"(b[0]), "r"(b[1]));
}

__device__ __forceinline__ void ldsm4(uint32_t* r, uint32_t addr){
    asm volatile("ldmatrix.sync.aligned.m8n8.x4.shared.b16 {%0,%1,%2,%3}, [%4];"
        : "=r"(r[0]), "=r"(r[1]), "=r"(r[2]), "=r"(r[3]) : "r"(addr));
}

// ---------------- alpha/beta GEMM body (runs inside mm0 grid) ----------------
#define ABSTG 23040
#define ABNKT (HH/32)

__device__ void ab_mma_body(__half* smem_ab,
                            const float* __restrict__ ba, const float* __restrict__ bb)
{
    const uint32_t sba = (uint32_t)__cvta_generic_to_shared(smem_ab);
    const int tid = threadIdx.x;
    const int wid = tid >> 5, lid = tid & 31;
    const int g = lid >> 2, tg = lid & 3;
    const int m0 = blockIdx.y * 128;

    float acc[4][4];
    #pragma unroll
    for (int a=0;a<4;a++)
        #pragma unroll
        for (int b=0;b<4;b++) acc[a][b] = 0.f;

    const uint32_t laneA = (uint32_t)((lid & 15)*80 + (lid >> 4)*16);
    const uint32_t laneB = (uint32_t)((((lid >> 4) & 1)*8 + (lid & 7))*80 + ((lid >> 3) & 1)*16);

    auto load_stage = [&](int kt){
        const uint32_t sb2 = sba + (uint32_t)((kt & 1) * ABSTG);
        const int k0 = kt * 32;
        for (int idx = tid; idx < 1152; idx += 256){
            uint32_t dst; const __half* src; size_t off;
            if (idx < 512){
                const int r = idx >> 2, c = idx & 3;
                dst = sb2 + (uint32_t)(r*80 + c*16);
                src = g_xhi; off = (size_t)(m0 + r)*HH + k0 + c*8;
            } else if (idx < 1024){
                const int q = idx - 512, r = q >> 2, c = q & 3;
                dst = sb2 + 10240 + (uint32_t)(r*80 + c*16);
                src = g_xlo; off = (size_t)(m0 + r)*HH + k0 + c*8;
            } else {
                const int q = idx - 1024, r = q >> 2, c = q & 3;
                dst = sb2 + 20480 + (uint32_t)(r*80 + c*16);
                src = g_abhi; off = (size_t)r*HH + k0 + c*8;
            }
            cp16(dst, src + off);
        }
        asm volatile("cp.async.commit_group;" ::: "memory");
    };

    load_stage(0);

    for (int kt = 0; kt < ABNKT; ++kt){
        if (kt + 1 < ABNKT) load_stage(kt + 1);
        if (kt + 1 < ABNKT) asm volatile("cp.async.wait_group 1;" ::: "memory");
        else                asm volatile("cp.async.wait_group 0;" ::: "memory");
        __syncthreads();

        const uint32_t base = sba + (uint32_t)((kt & 1) * ABSTG);
        const uint32_t aAh = base +         laneA + (uint32_t)(wid*16)*80;
        const uint32_t aAl = base + 10240 + laneA + (uint32_t)(wid*16)*80;
        const uint32_t aBh = base + 20480 + laneB;

        #pragma unroll
        for (int ks = 0; ks < 2; ++ks){
            const uint32_t kb = (uint32_t)(ks*32);
            uint32_t bh[4][2];
            {
                uint32_t r[4];
                ldsm4(r, aBh + kb);
                bh[0][0]=r[0]; bh[0][1]=r[1]; bh[1][0]=r[2]; bh[1][1]=r[3];
                ldsm4(r, aBh + kb + 16*80);
                bh[2][0]=r[0]; bh[2][1]=r[1]; bh[3][0]=r[2]; bh[3][1]=r[3];
            }
            uint32_t af[4];
            ldsm4(af, aAh + kb);
            #pragma unroll
            for (int nt = 0; nt < 4; ++nt)
                mma16816(acc[nt], af, bh[nt]);
            ldsm4(af, aAl + kb);
            #pragma unroll
            for (int nt = 0; nt < 4; ++nt)
                mma16816(acc[nt], af, bh[nt]);
        }
        __syncthreads();
    }

    const int r0 = m0 + wid*16 + g;
    #pragma unroll
    for (int nt = 0; nt < 4; ++nt){
        const int n = nt*8 + 2*tg;
        #pragma unroll
        for (int e = 0; e < 2; ++e){
            const int nn = n + e;
            const float bias = (nn < NH) ? ba[nn] : bb[nn - NH];
            float v0 = sigmoidf_(acc[nt][e]     + bias);
            float v1 = sigmoidf_(acc[nt][e + 2] + bias);
            if (nn < NH){
                g_alpha[r0*NH + nn]     = v0;
                g_alpha[(r0+8)*NH + nn] = v1;
            } else {
                g_beta[r0*NH + nn - NH]     = v0;
                g_beta[(r0+8)*NH + nn - NH] = v1;
            }
        }
    }
}

// ---------------- main GEMM: fp16 2-term, K32, 3-stage ring, wait 1 ----------
#define RSTG 10240
#define MMSTG (3*RSTG)          // 30720
#define MM_SMEM (3*MMSTG)       // 92160
#define NKT (HH/32)             // 32

__global__ void __launch_bounds__(256, 2) mm_kernel(int mode, float* __restrict__ Cext,
                                                    const float* __restrict__ ba,
                                                    const float* __restrict__ bb)
{
    extern __shared__ __align__(16) __half smem_h[];

    if (mode == 0 && blockIdx.x == 32){
        ab_mma_body(smem_h, ba, bb);
        return;
    }

    const uint32_t sba = (uint32_t)__cvta_generic_to_shared(smem_h);
    const int tid = threadIdx.x;
    const int wid = tid >> 5, lid = tid & 31;
    const int g = lid >> 2, tg = lid & 3;
    const int wm = wid & 1, wn = wid >> 1;

    const int m0 = blockIdx.y * 128;
    const int n0 = blockIdx.x * 128;
    const int wrow = (mode ? 4096 : 0) + n0;
    const __half* Ah = mode ? g_ahi : g_xhi;
    const __half* Al = mode ? g_alo : g_xlo;

    float acc[4][4][4];
    #pragma unroll
    for (int a=0;a<4;a++)
        #pragma unroll
        for (int b=0;b<4;b++)
            #pragma unroll
            for (int c=0;c<4;c++) acc[a][b][c] = 0.f;

    const uint32_t laneA = (uint32_t)((lid & 15)*80 + (lid >> 4)*16);
    const uint32_t laneB = (uint32_t)((((lid >> 4) & 1)*8 + (lid & 7))*80 + ((lid >> 3) & 1)*16);

    auto load_stage = [&](int kt, int buf){
        const uint32_t sb2 = sba + (uint32_t)(buf * MMSTG);
        const int k0 = kt * 32;
        #pragma unroll
        for (int half = 0; half < 2; ++half){
            const int ch = tid + 256*half;      // 0..511
            const int row = ch >> 2, c16 = ch & 3;
            const uint32_t d = (uint32_t)(row*80 + c16*16);
            const size_t ka = (size_t)k0 + c16*8;
            const size_t aoff = (size_t)(m0 + row)*HH + ka;
            const size_t boff = (size_t)(wrow + row)*HH + ka;
            cp16(sb2 + d,           Ah    + aoff);
            cp16(sb2 + RSTG + d,    Al    + aoff);
            cp16(sb2 + 2*RSTG + d,  g_whi + boff);
        }
    };

    load_stage(0, 0); asm volatile("cp.async.commit_group;" ::: "memory");
    load_stage(1, 1); asm volatile("cp.async.commit_group;" ::: "memory");

    int buf = 0;
    for (int kt = 0; kt < NKT; ++kt){
        asm volatile("cp.async.wait_group 1;" ::: "memory");
        __syncthreads();
        if (kt + 2 < NKT) load_stage(kt + 2, (buf + 2 >= 3) ? buf - 1 : buf + 2);
        asm volatile("cp.async.commit_group;" ::: "memory");

        const uint32_t stgb = sba + (uint32_t)(buf * MMSTG);
        const uint32_t aAh = stgb +           laneA + (uint32_t)(wm*64)*80;
        const uint32_t aAl = stgb + RSTG    + laneA + (uint32_t)(wm*64)*80;
        const uint32_t aBh = stgb + 2*RSTG  + laneB + (uint32_t)(wn*32)*80;

        uint32_t bh[2][4][2];
        #pragma unroll
        for (int ks = 0; ks < 2; ++ks){
            const uint32_t kb = (uint32_t)(ks*32);
            uint32_t r[4];
            ldsm4(r, aBh + kb);
            bh[ks][0][0]=r[0]; bh[ks][0][1]=r[1]; bh[ks][1][0]=r[2]; bh[ks][1][1]=r[3];
            ldsm4(r, aBh + kb + 16*80);
            bh[ks][2][0]=r[0]; bh[ks][2][1]=r[1]; bh[ks][3][0]=r[2]; bh[ks][3][1]=r[3];
        }

        #pragma unroll
        for (int ks = 0; ks < 2; ++ks){
            const uint32_t kb = (uint32_t)(ks*32);
            #pragma unroll
            for (int mt = 0; mt < 4; ++mt){
                uint32_t af[4];
                ldsm4(af, aAh + kb + (uint32_t)(mt*16)*80);
                #pragma unroll
                for (int nt = 0; nt < 4; ++nt)
                    mma16816(acc[mt][nt], af, bh[ks][nt]);
                ldsm4(af, aAl + kb + (uint32_t)(mt*16)*80);
                #pragma unroll
                for (int nt = 0; nt < 4; ++nt)
                    mma16816(acc[mt][nt], af, bh[ks][nt]);
            }
        }
        buf = (buf + 1 >= 3) ? 0 : buf + 1;
    }

    float* dst; int epi = 0; int colb;
    if (mode == 0){
        const int mat = n0 >> 10;
        colb = n0 & 1023;
        switch (mat){
            case 0: dst = g_q; break;
            case 1: dst = g_k; break;
            case 2: dst = g_v; epi = 1; break;
            default: dst = g_g; epi = 1; break;
        }
    } else { dst = Cext; colb = n0; }

    #pragma unroll
    for (int mt = 0; mt < 4; ++mt){
        const int r = m0 + wm*64 + mt*16 + g;
        #pragma unroll
        for (int nt = 0; nt < 4; ++nt){
            const int cidx = colb + wn*32 + nt*8 + 2*tg;
            float v0 = acc[mt][nt][0], v1 = acc[mt][nt][1];
            float v2 = acc[mt][nt][2], v3 = acc[mt][nt][3];
            if (epi){
                v0 *= sigmoidf_(v0); v1 *= sigmoidf_(v1);
                v2 *= sigmoidf_(v2); v3 *= sigmoidf_(v3);
            }
            *reinterpret_cast<float2*>(dst + (size_t)r*HH + cidx)     = make_float2(v0, v1);
            *reinterpret_cast<float2*>(dst + (size_t)(r+8)*HH + cidx) = make_float2(v2, v3);
        }
    }
}

// ---------------- in-smem per-row L2 normalize helper -------------------------
__device__ __forceinline__ void l2norm_smem(float* buf, int w, int l)
{
    const int row = w*4 + (l >> 3);
    const int col = (l & 7) * 8;
    float* p = buf + row*HD + col;
    const float4 a0 = *reinterpret_cast<const float4*>(p);
    const float4 a1 = *reinterpret_cast<const float4*>(p + 4);
    float ss = a0.x*a0.x + a0.y*a0.y + a0.z*a0.z + a0.w*a0.w
             + a1.x*a1.x + a1.y*a1.y + a1.z*a1.z + a1.w*a1.w;
    ss += __shfl_xor_sync(0xffffffffu, ss, 1);
    ss += __shfl_xor_sync(0xffffffffu, ss, 2);
    ss += __shfl_xor_sync(0xffffffffu, ss, 4);
    const float inv = 1.f / fmaxf(sqrtf(ss), 1e-12f);
    *reinterpret_cast<float4*>(p)     = make_float4(a0.x*inv, a0.y*inv, a0.z*inv, a0.w*inv);
    *reinterpret_cast<float4*>(p + 4) = make_float4(a1.x*inv, a1.y*inv, a1.z*inv, a1.w*inv);
}

// ---------------- recurrence pass 1 (fused k-normalization) -------------------
__global__ void __launch_bounds__(512) pass1_kernel()
{
    const int c = blockIdx.x, bh = blockIdx.y;
    const int b = bh >> 4, h = bh & 15;
    const int tid = threadIdx.x;
    const int w = tid >> 5, l = tid & 31;
    __shared__ __align__(16) float ks[CHUNK*HD];
    __shared__ __align__(16) float vs[CHUNK*HD];
    __shared__ float aa[CHUNK], bbs[CHUNK];

    const int row0 = b*SS + c*CHUNK;
    for (int idx = tid; idx < CHUNK*16; idx += 512){
        const int t = idx >> 4, c4 = (idx & 15) * 4;
        const size_t go = (size_t)(row0 + t)*HH + h*HD + c4;
        *reinterpret_cast<float4*>(&ks[t*HD + c4]) = *reinterpret_cast<const float4*>(&g_k[go]);
        *reinterpret_cast<float4*>(&vs[t*HD + c4]) = *reinterpret_cast<const float4*>(&g_v[go]);
    }
    if (tid < CHUNK){
        aa[tid]  = g_alpha[(row0 + tid)*NH + h];
        bbs[tid] = g_beta [(row0 + tid)*NH + h];
    }
    __syncthreads();
    l2norm_smem(ks, w, l);
    __syncthreads();

    float M[4][2], Cc[4][2];
    #pragma unroll
    for (int r=0;r<4;r++){ M[r][0]=1.f; M[r][1]=1.f; Cc[r][0]=0.f; Cc[r][1]=0.f; }

    #pragma unroll 2
    for (int t=0;t<CHUNK;++t){
        const float a = aa[t], bt = bbs[t], abp = a*bt;
        const float kj0 = ks[t*HD + l], kj1 = ks[t*HD + l + 32];
        #pragma unroll
        for (int r=0;r<4;r++){
            const int i = w*4 + r;
            const float ki = ks[t*HD + i];
            const float bvi = bt * vs[t*HD + i];
            const float abki = abp * ki;
            const float m0 = fmaf(-abki, kj0, a);
            const float m1 = fmaf(-abki, kj1, a);
            M[r][0] *= m0;  M[r][1] *= m1;
            Cc[r][0] = fmaf(m0, Cc[r][0], bvi*kj0);
            Cc[r][1] = fmaf(m1, Cc[r][1], bvi*kj1);
        }
    }
    const size_t ob = ((size_t)bh*NCHUNK + c) * SE;
    #pragma unroll
    for (int r=0;r<4;r++){
        const int i = w*4 + r;
        g_M [ob + i*HD + l]      = M[r][0];
        g_M [ob + i*HD + l + 32] = M[r][1];
        g_Cc[ob + i*HD + l]      = Cc[r][0];
        g_Cc[ob + i*HD + l + 32] = Cc[r][1];
    }
}

// ---------------- serial scan: batch-load all chunks, serial FMA chain -------
// 512 blocks x 512 threads: one element chain per thread.
__global__ void __launch_bounds__(512) scan_kernel()
{
    const int e = blockIdx.x*512 + threadIdx.x;       // 0 .. BHDIM*SE-1
    const int bh = e >> 12;                           // /SE
    const int elem = e & (SE-1);
    const size_t base = (size_t)bh*NCHUNK*SE + elem;

    float m[NCHUNK], cc[NCHUNK];
    #pragma unroll
    for (int c = 0; c < NCHUNK; ++c){
        m[c]  = g_M [base + (size_t)c*SE];
        cc[c] = g_Cc[base + (size_t)c*SE];
    }
    float s = 0.f;
    #pragma unroll
    for (int c = 0; c < NCHUNK; ++c){
        g_S0[base + (size_t)c*SE] = s;
        s = fmaf(m[c], s, cc[c]);
    }
}

// ---------------- recurrence pass 2 (fused k,q normalization) -----------------
#define P2_SMEM (4*CHUNK*HD*4 + 2*CHUNK*4)   // 66048 B
__global__ void __launch_bounds__(512) pass2_kernel()
{
    const int c = blockIdx.x, bh = blockIdx.y;
    const int b = bh >> 4, h = bh & 15;
    const int tid = threadIdx.x;
    const int w = tid >> 5, l = tid & 31;
    extern __shared__ __align__(16) float p2s[];
    float* ks  = p2s;
    float* vs  = p2s + CHUNK*HD;
    float* qs  = p2s + 2*CHUNK*HD;
    float* outs= p2s + 3*CHUNK*HD;
    float* aa  = p2s + 4*CHUNK*HD;
    float* bbs = aa + CHUNK;

    const int row0 = b*SS + c*CHUNK;
    for (int idx = tid; idx < CHUNK*16; idx += 512){
        const int t = idx >> 4, c4 = (idx & 15) * 4;
        const size_t go = (size_t)(row0 + t)*HH + h*HD + c4;
        *reinterpret_cast<float4*>(&ks[t*HD + c4]) = *reinterpret_cast<const float4*>(&g_k[go]);
        *reinterpret_cast<float4*>(&vs[t*HD + c4]) = *reinterpret_cast<const float4*>(&g_v[go]);
        *reinterpret_cast<float4*>(&qs[t*HD + c4]) = *reinterpret_cast<const float4*>(&g_q[go]);
    }
    if (tid < CHUNK){
        aa[tid]  = g_alpha[(row0 + tid)*NH + h];
        bbs[tid] = g_beta [(row0 + tid)*NH + h];
    }

    float st[4][2];
    const size_t sbg = ((size_t)bh*NCHUNK + c) * SE;
    #pragma unroll
    for (int r=0;r<4;r++){
        const int i = w*4 + r;
        st[r][0] = g_S0[sbg + i*HD + l];
        st[r][1] = g_S0[sbg + i*HD + l + 32];
    }
    __syncthreads();
    l2norm_smem(ks, w, l);
    l2norm_smem(qs, w, l);
    __syncthreads();

    #pragma unroll 2
    for (int t=0;t<CHUNK;++t){
        const float a = aa[t], bt = bbs[t], abp = a*bt;
        const float kj0 = ks[t*HD + l], kj1 = ks[t*HD + l + 32];
        const float qj0 = qs[t*HD + l], qj1 = qs[t*HD + l + 32];
        float p[4];
        #pragma unroll
        for (int r=0;r<4;r++){
            const int i = w*4 + r;
            const float ki = ks[t*HD + i];
            const float bvi = bt * vs[t*HD + i];
            const float abki = abp * ki;
            const float m0 = fmaf(-abki, kj0, a);
            const float m1 = fmaf(-abki, kj1, a);
            st[r][0] = fmaf(m0, st[r][0], bvi*kj0);
            st[r][1] = fmaf(m1, st[r][1], bvi*kj1);
            p[r] = fmaf(st[r][0], qj0, st[r][1]*qj1);
        }
        #pragma unroll
        for (int o=16;o;o>>=1){
            p[0] += __shfl_xor_sync(0xffffffffu, p[0], o);
            p[1] += __shfl_xor_sync(0xffffffffu, p[1], o);
            p[2] += __shfl_xor_sync(0xffffffffu, p[2], o);
            p[3] += __shfl_xor_sync(0xffffffffu, p[3], o);
        }
        if (l < 4) outs[t*HD + w*4 + l] = p[l];
    }
    __syncthreads();
    for (int idx = tid; idx < CHUNK*16; idx += 512){
        const int t = idx >> 4, c4 = (idx & 15) * 4;
        const size_t go = (size_t)(row0 + t)*HH + h*HD + c4;
        *reinterpret_cast<float4*>(&g_attn[go]) = *reinterpret_cast<const float4*>(&outs[t*HD + c4]);
    }
}

// ---------------- LayerNorm + SiLU-gate + fp16 split (fused, vectorized) -----
__global__ void __launch_bounds__(256) ln_gate_kernel(
    const float* __restrict__ lng, const float* __restrict__ lnb)
{
    const int r = blockIdx.x, tid = threadIdx.x;
    __shared__ __align__(16) float xs[HH];
    __shared__ float red[8];
    const float* row = g_attn + (size_t)r*HH;
    float s = 0.f;
    for (int i = tid*4; i < HH; i += 256*4){
        float4 v = *reinterpret_cast<const float4*>(row + i);
        *reinterpret_cast<float4*>(&xs[i]) = v;
        s += (v.x + v.y) + (v.z + v.w);
    }
    #pragma unroll
    for (int o=16;o;o>>=1) s += __shfl_xor_sync(0xffffffffu, s, o);
    if ((tid & 31) == 0) red[tid>>5] = s;
    __syncthreads();
    float tot = red[0]+red[1]+red[2]+red[3]+red[4]+red[5]+red[6]+red[7];
    const float mu = tot * (1.f/HH);
    __syncthreads();
    float vsum = 0.f;
    for (int i = tid*4; i < HH; i += 256*4){
        float4 v = *reinterpret_cast<const float4*>(&xs[i]);
        float d0 = v.x-mu, d1 = v.y-mu, d2 = v.z-mu, d3 = v.w-mu;
        vsum = fmaf(d0,d0, fmaf(d1,d1, fmaf(d2,d2, fmaf(d3,d3, vsum))));
    }
    #pragma unroll
    for (int o=16;o;o>>=1) vsum += __shfl_xor_sync(0xffffffffu, vsum, o);
    if ((tid & 31) == 0) red[tid>>5] = vsum;
    __syncthreads();
    float vtot = red[0]+red[1]+red[2]+red[3]+red[4]+red[5]+red[6]+red[7];
    const float rstd = rsqrtf(vtot*(1.f/HH) + 1e-5f);
    for (int i=tid*4;i<HH;i+=256*4){
        float4 gv = *reinterpret_cast<const float4*>(g_g + (size_t)r*HH + i);
        float4 lg = *reinterpret_cast<const float4*>(lng + i);
        float4 lb = *reinterpret_cast<const float4*>(lnb + i);
        float4 xv = *reinterpret_cast<const float4*>(&xs[i]);
        float4 yv;
        yv.x = ((xv.x-mu)*rstd*lg.x + lb.x) * gv.x;
        yv.y = ((xv.y-mu)*rstd*lg.y + lb.y) * gv.y;
        yv.z = ((xv.z-mu)*rstd*lg.z + lb.z) * gv.z;
        yv.w = ((xv.w-mu)*rstd*lg.w + lb.w) * gv.w;
        split4h(yv, g_ahi + (size_t)r*HH + i, g_alo + (size_t)r*HH + i);
    }
}

// ---------------- launch -----------------------------------------------------
extern "C" void kernel_launch(void* const* d_in, const int* in_sizes, int n_in,
                              void* d_out, int out_size)
{
    const float* x   = (const float*)d_in[0];
    const float* Wq  = (const float*)d_in[1];
    const float* Wk  = (const float*)d_in[2];
    const float* Wv  = (const float*)d_in[3];
    const float* Wa  = (const float*)d_in[4];
    const float* ba  = (const float*)d_in[5];
    const float* Wb  = (const float*)d_in[6];
    const float* bb  = (const float*)d_in[7];
    const float* Wg  = (const float*)d_in[8];
    const float* Wo  = (const float*)d_in[9];
    const float* lng = (const float*)d_in[10];
    const float* lnb = (const float*)d_in[11];
    float* out = (float*)d_out;

    cudaFuncSetAttribute(mm_kernel, cudaFuncAttributeMaxDynamicSharedMemorySize, MM_SMEM);
    cudaFuncSetAttribute(pass2_kernel, cudaFuncAttributeMaxDynamicSharedMemorySize, P2_SMEM);

    cvt_all_kernel<<<(CVT_TOT+255)/256, 256>>>(x, Wq, Wk, Wv, Wg, Wo, Wa, Wb);
    mm_kernel<<<dim3(33, 64), 256, MM_SMEM>>>(0, nullptr, ba, bb);  // QKVG + alpha/beta
    pass1_kernel<<<dim3(NCHUNK, BHDIM), 512>>>();
    scan_kernel<<<(BHDIM*SE)/512, 512>>>();
    pass2_kernel<<<dim3(NCHUNK, BHDIM), 512, P2_SMEM>>>();
    ln_gate_kernel<<<NROWS, 256>>>(lng, lnb);
    mm_kernel<<<dim3(8, 64), 256, MM_SMEM>>>(1, out, nullptr, nullptr);
}

// round 15
// speedup vs baseline: 1.2855x; 1.0012x over previous
#include <cuda_runtime.h>
#include <cuda_fp16.h>
#include <cstdint>

// Problem constants
#define BB 4
#define SS 2048
#define HH 1024
#define NH 16
#define HD 64
#define NROWS (BB*SS)          // 8192
#define CHUNK 64
#define NCHUNK (SS/CHUNK)      // 32
#define BHDIM (BB*NH)          // 64
#define SE (HD*HD)             // 4096

// ---------------- scratch (static __device__, allocation-free) ----------------
__device__ __align__(16) float g_q[(size_t)NROWS*HH];
__device__ __align__(16) float g_k[(size_t)NROWS*HH];
__device__ __align__(16) float g_v[(size_t)NROWS*HH];
__device__ __align__(16) float g_g[(size_t)NROWS*HH];
__device__ __align__(16) float g_attn[(size_t)NROWS*HH];
__device__ float g_alpha[NROWS*NH];
__device__ float g_beta[NROWS*NH];
__device__ __align__(16) float g_M [(size_t)BHDIM*NCHUNK*SE];
__device__ __align__(16) float g_Cc[(size_t)BHDIM*NCHUNK*SE];
__device__ __align__(16) float g_S0[(size_t)BHDIM*NCHUNK*SE];

// fp16 split buffers (A side: hi+lo; B side: hi only)
__device__ __align__(16) __half g_xhi[(size_t)NROWS*HH];
__device__ __align__(16) __half g_xlo[(size_t)NROWS*HH];
__device__ __align__(16) __half g_whi[(size_t)5*HH*HH];
__device__ __align__(16) __half g_ahi[(size_t)NROWS*HH];
__device__ __align__(16) __half g_alo[(size_t)NROWS*HH];
__device__ __align__(16) __half g_abhi[2*NH*HH];

__device__ __forceinline__ float sigmoidf_(float z){ return 1.f/(1.f+expf(-z)); }

__device__ __forceinline__ void split4h(float4 v, __half* hi, __half* lo){
    float f[4] = {v.x, v.y, v.z, v.w};
    __half h[4], l[4];
    #pragma unroll
    for (int j=0;j<4;j++){
        h[j] = __float2half_rn(f[j]);
        l[j] = __float2half_rn(f[j] - __half2float(h[j]));
    }
    reinterpret_cast<__half2*>(hi)[0] = __halves2half2(h[0], h[1]);
    reinterpret_cast<__half2*>(hi)[1] = __halves2half2(h[2], h[3]);
    reinterpret_cast<__half2*>(lo)[0] = __halves2half2(l[0], l[1]);
    reinterpret_cast<__half2*>(lo)[1] = __halves2half2(l[2], l[3]);
}

__device__ __forceinline__ void cvt4h(float4 v, __half* hi){
    reinterpret_cast<__half2*>(hi)[0] = __halves2half2(__float2half_rn(v.x), __float2half_rn(v.y));
    reinterpret_cast<__half2*>(hi)[1] = __halves2half2(__float2half_rn(v.z), __float2half_rn(v.w));
}

// ---------------- fused fp32 -> fp16 conversion (x split | 5 W hi | Wab hi) --
#define XN4 ((NROWS*HH)/4)      // 2097152
#define WN4 ((HH*HH)/4)         // 262144
#define QN4 ((NH*HH)/4)         // 4096
#define CVT_TOT (XN4 + 5*WN4 + 2*QN4)

__global__ void __launch_bounds__(256) cvt_all_kernel(
    const float* __restrict__ x,
    const float* __restrict__ W0, const float* __restrict__ W1,
    const float* __restrict__ W2, const float* __restrict__ W3,
    const float* __restrict__ W4,
    const float* __restrict__ Wa, const float* __restrict__ Wb)
{
    const int i = blockIdx.x*256 + threadIdx.x;
    if (i >= CVT_TOT) return;
    if (i < XN4){
        split4h(reinterpret_cast<const float4*>(x)[i], g_xhi + 4*(size_t)i, g_xlo + 4*(size_t)i);
    } else if (i < XN4 + 5*WN4){
        const int j5 = i - XN4;
        const int mat = j5 / WN4, j = j5 - mat*WN4;
        const float* src;
        switch (mat){
            case 0: src = W0; break; case 1: src = W1; break;
            case 2: src = W2; break; case 3: src = W3; break;
            default: src = W4; break;
        }
        cvt4h(reinterpret_cast<const float4*>(src)[j], g_whi + (size_t)mat*HH*HH + 4*(size_t)j);
    } else {
        const int j = i - XN4 - 5*WN4;
        float4 v = (j < QN4) ? reinterpret_cast<const float4*>(Wa)[j]
                             : reinterpret_cast<const float4*>(Wb)[j-QN4];
        cvt4h(v, g_abhi + 4*(size_t)j);
    }
}

// ---------------- common mma/ldsm/cp helpers ---------------------------------
__device__ __forceinline__ void cp16(uint32_t smem, const void* gptr){
    const unsigned long long g = (unsigned long long)__cvta_generic_to_global(gptr);
    asm volatile("cp.async.cg.shared.global [%0], [%1], 16;" :: "r"(smem), "l"(g) : "memory");
}

__device__ __forceinline__ void mma16816(float* c, const uint32_t* a, const uint32_t* b){
    asm volatile("mma.sync.aligned.m16n8k16.row.col.f32.f16.f16.f32 "
        "{%0,%1,%2,%3}, {%4,%5,%6,%7}, {%8,%9}, {%0,%1,%2,%3};"
        : "+f"(c[0]), "+f"(c[1]), "+f"(c[2]), "+f"(c[3])
        : "r"(a[0]), "r"(a[1]), "r"(a[2]), "r"(a[3]), "r"(b[0]), "r"(b[1]));
}

__device__ __forceinline__ void ldsm4(uint32_t* r, uint32_t addr){
    asm volatile("ldmatrix.sync.aligned.m8n8.x4.shared.b16 {%0,%1,%2,%3}, [%4];"
        : "=r"(r[0]), "=r"(r[1]), "=r"(r[2]), "=r"(r[3]) : "r"(addr));
}

// ---------------- alpha/beta GEMM body (runs inside mm0 grid) ----------------
#define ABSTG 23040
#define ABNKT (HH/32)

__device__ void ab_mma_body(__half* smem_ab,
                            const float* __restrict__ ba, const float* __restrict__ bb)
{
    const uint32_t sba = (uint32_t)__cvta_generic_to_shared(smem_ab);
    const int tid = threadIdx.x;
    const int wid = tid >> 5, lid = tid & 31;
    const int g = lid >> 2, tg = lid & 3;
    const int m0 = blockIdx.y * 128;

    float acc[4][4];
    #pragma unroll
    for (int a=0;a<4;a++)
        #pragma unroll
        for (int b=0;b<4;b++) acc[a][b] = 0.f;

    const uint32_t laneA = (uint32_t)((lid & 15)*80 + (lid >> 4)*16);
    const uint32_t laneB = (uint32_t)((((lid >> 4) & 1)*8 + (lid & 7))*80 + ((lid >> 3) & 1)*16);

    auto load_stage = [&](int kt){
        const uint32_t sb2 = sba + (uint32_t)((kt & 1) * ABSTG);
        const int k0 = kt * 32;
        for (int idx = tid; idx < 1152; idx += 256){
            uint32_t dst; const __half* src; size_t off;
            if (idx < 512){
                const int r = idx >> 2, c = idx & 3;
                dst = sb2 + (uint32_t)(r*80 + c*16);
                src = g_xhi; off = (size_t)(m0 + r)*HH + k0 + c*8;
            } else if (idx < 1024){
                const int q = idx - 512, r = q >> 2, c = q & 3;
                dst = sb2 + 10240 + (uint32_t)(r*80 + c*16);
                src = g_xlo; off = (size_t)(m0 + r)*HH + k0 + c*8;
            } else {
                const int q = idx - 1024, r = q >> 2, c = q & 3;
                dst = sb2 + 20480 + (uint32_t)(r*80 + c*16);
                src = g_abhi; off = (size_t)r*HH + k0 + c*8;
            }
            cp16(dst, src + off);
        }
        asm volatile("cp.async.commit_group;" ::: "memory");
    };

    load_stage(0);

    for (int kt = 0; kt < ABNKT; ++kt){
        if (kt + 1 < ABNKT) load_stage(kt + 1);
        if (kt + 1 < ABNKT) asm volatile("cp.async.wait_group 1;" ::: "memory");
        else                asm volatile("cp.async.wait_group 0;" ::: "memory");
        __syncthreads();

        const uint32_t base = sba + (uint32_t)((kt & 1) * ABSTG);
        const uint32_t aAh = base +         laneA + (uint32_t)(wid*16)*80;
        const uint32_t aAl = base + 10240 + laneA + (uint32_t)(wid*16)*80;
        const uint32_t aBh = base + 20480 + laneB;

        #pragma unroll
        for (int ks = 0; ks < 2; ++ks){
            const uint32_t kb = (uint32_t)(ks*32);
            uint32_t bh[4][2];
            {
                uint32_t r[4];
                ldsm4(r, aBh + kb);
                bh[0][0]=r[0]; bh[0][1]=r[1]; bh[1][0]=r[2]; bh[1][1]=r[3];
                ldsm4(r, aBh + kb + 16*80);
                bh[2][0]=r[0]; bh[2][1]=r[1]; bh[3][0]=r[2]; bh[3][1]=r[3];
            }
            uint32_t af[4];
            ldsm4(af, aAh + kb);
            #pragma unroll
            for (int nt = 0; nt < 4; ++nt)
                mma16816(acc[nt], af, bh[nt]);
            ldsm4(af, aAl + kb);
            #pragma unroll
            for (int nt = 0; nt < 4; ++nt)
                mma16816(acc[nt], af, bh[nt]);
        }
        __syncthreads();
    }

    const int r0 = m0 + wid*16 + g;
    #pragma unroll
    for (int nt = 0; nt < 4; ++nt){
        const int n = nt*8 + 2*tg;
        #pragma unroll
        for (int e = 0; e < 2; ++e){
            const int nn = n + e;
            const float bias = (nn < NH) ? ba[nn] : bb[nn - NH];
            float v0 = sigmoidf_(acc[nt][e]     + bias);
            float v1 = sigmoidf_(acc[nt][e + 2] + bias);
            if (nn < NH){
                g_alpha[r0*NH + nn]     = v0;
                g_alpha[(r0+8)*NH + nn] = v1;
            } else {
                g_beta[r0*NH + nn - NH]     = v0;
                g_beta[(r0+8)*NH + nn - NH] = v1;
            }
        }
    }
}

// ---------------- main GEMM: fp16 2-term, K32, 3-stage ring, wait 1 ----------
#define RSTG 10240
#define MMSTG (3*RSTG)          // 30720
#define MM_SMEM (3*MMSTG)       // 92160
#define NKT (HH/32)             // 32

__global__ void __launch_bounds__(256, 2) mm_kernel(int mode, float* __restrict__ Cext,
                                                    const float* __restrict__ ba,
                                                    const float* __restrict__ bb)
{
    extern __shared__ __align__(16) __half smem_h[];

    if (mode == 0 && blockIdx.x == 32){
        ab_mma_body(smem_h, ba, bb);
        return;
    }

    const uint32_t sba = (uint32_t)__cvta_generic_to_shared(smem_h);
    const int tid = threadIdx.x;
    const int wid = tid >> 5, lid = tid & 31;
    const int g = lid >> 2, tg = lid & 3;
    const int wm = wid & 1, wn = wid >> 1;

    const int m0 = blockIdx.y * 128;
    const int n0 = blockIdx.x * 128;
    const int wrow = (mode ? 4096 : 0) + n0;
    const __half* Ah = mode ? g_ahi : g_xhi;
    const __half* Al = mode ? g_alo : g_xlo;

    float acc[4][4][4];
    #pragma unroll
    for (int a=0;a<4;a++)
        #pragma unroll
        for (int b=0;b<4;b++)
            #pragma unroll
            for (int c=0;c<4;c++) acc[a][b][c] = 0.f;

    const uint32_t laneA = (uint32_t)((lid & 15)*80 + (lid >> 4)*16);
    const uint32_t laneB = (uint32_t)((((lid >> 4) & 1)*8 + (lid & 7))*80 + ((lid >> 3) & 1)*16);

    auto load_stage = [&](int kt, int buf){
        const uint32_t sb2 = sba + (uint32_t)(buf * MMSTG);
        const int k0 = kt * 32;
        #pragma unroll
        for (int half = 0; half < 2; ++half){
            const int ch = tid + 256*half;      // 0..511
            const int row = ch >> 2, c16 = ch & 3;
            const uint32_t d = (uint32_t)(row*80 + c16*16);
            const size_t ka = (size_t)k0 + c16*8;
            const size_t aoff = (size_t)(m0 + row)*HH + ka;
            const size_t boff = (size_t)(wrow + row)*HH + ka;
            cp16(sb2 + d,           Ah    + aoff);
            cp16(sb2 + RSTG + d,    Al    + aoff);
            cp16(sb2 + 2*RSTG + d,  g_whi + boff);
        }
    };

    load_stage(0, 0); asm volatile("cp.async.commit_group;" ::: "memory");
    load_stage(1, 1); asm volatile("cp.async.commit_group;" ::: "memory");

    int buf = 0;
    for (int kt = 0; kt < NKT; ++kt){
        asm volatile("cp.async.wait_group 1;" ::: "memory");
        __syncthreads();
        if (kt + 2 < NKT) load_stage(kt + 2, (buf + 2 >= 3) ? buf - 1 : buf + 2);
        asm volatile("cp.async.commit_group;" ::: "memory");

        const uint32_t stgb = sba + (uint32_t)(buf * MMSTG);
        const uint32_t aAh = stgb +           laneA + (uint32_t)(wm*64)*80;
        const uint32_t aAl = stgb + RSTG    + laneA + (uint32_t)(wm*64)*80;
        const uint32_t aBh = stgb + 2*RSTG  + laneB + (uint32_t)(wn*32)*80;

        uint32_t bh[2][4][2];
        #pragma unroll
        for (int ks = 0; ks < 2; ++ks){
            const uint32_t kb = (uint32_t)(ks*32);
            uint32_t r[4];
            ldsm4(r, aBh + kb);
            bh[ks][0][0]=r[0]; bh[ks][0][1]=r[1]; bh[ks][1][0]=r[2]; bh[ks][1][1]=r[3];
            ldsm4(r, aBh + kb + 16*80);
            bh[ks][2][0]=r[0]; bh[ks][2][1]=r[1]; bh[ks][3][0]=r[2]; bh[ks][3][1]=r[3];
        }

        #pragma unroll
        for (int ks = 0; ks < 2; ++ks){
            const uint32_t kb = (uint32_t)(ks*32);
            #pragma unroll
            for (int mt = 0; mt < 4; ++mt){
                uint32_t af[4];
                ldsm4(af, aAh + kb + (uint32_t)(mt*16)*80);
                #pragma unroll
                for (int nt = 0; nt < 4; ++nt)
                    mma16816(acc[mt][nt], af, bh[ks][nt]);
                ldsm4(af, aAl + kb + (uint32_t)(mt*16)*80);
                #pragma unroll
                for (int nt = 0; nt < 4; ++nt)
                    mma16816(acc[mt][nt], af, bh[ks][nt]);
            }
        }
        buf = (buf + 1 >= 3) ? 0 : buf + 1;
    }

    float* dst; int epi = 0; int colb;
    if (mode == 0){
        const int mat = n0 >> 10;
        colb = n0 & 1023;
        switch (mat){
            case 0: dst = g_q; break;
            case 1: dst = g_k; break;
            case 2: dst = g_v; epi = 1; break;
            default: dst = g_g; epi = 1; break;
        }
    } else { dst = Cext; colb = n0; }

    #pragma unroll
    for (int mt = 0; mt < 4; ++mt){
        const int r = m0 + wm*64 + mt*16 + g;
        #pragma unroll
        for (int nt = 0; nt < 4; ++nt){
            const int cidx = colb + wn*32 + nt*8 + 2*tg;
            float v0 = acc[mt][nt][0], v1 = acc[mt][nt][1];
            float v2 = acc[mt][nt][2], v3 = acc[mt][nt][3];
            if (epi){
                v0 *= sigmoidf_(v0); v1 *= sigmoidf_(v1);
                v2 *= sigmoidf_(v2); v3 *= sigmoidf_(v3);
            }
            *reinterpret_cast<float2*>(dst + (size_t)r*HH + cidx)     = make_float2(v0, v1);
            *reinterpret_cast<float2*>(dst + (size_t)(r+8)*HH + cidx) = make_float2(v2, v3);
        }
    }
}

// ---------------- in-smem per-row L2 normalize helper -------------------------
__device__ __forceinline__ void l2norm_smem(float* buf, int w, int l)
{
    const int row = w*4 + (l >> 3);
    const int col = (l & 7) * 8;
    float* p = buf + row*HD + col;
    const float4 a0 = *reinterpret_cast<const float4*>(p);
    const float4 a1 = *reinterpret_cast<const float4*>(p + 4);
    float ss = a0.x*a0.x + a0.y*a0.y + a0.z*a0.z + a0.w*a0.w
             + a1.x*a1.x + a1.y*a1.y + a1.z*a1.z + a1.w*a1.w;
    ss += __shfl_xor_sync(0xffffffffu, ss, 1);
    ss += __shfl_xor_sync(0xffffffffu, ss, 2);
    ss += __shfl_xor_sync(0xffffffffu, ss, 4);
    const float inv = 1.f / fmaxf(sqrtf(ss), 1e-12f);
    *reinterpret_cast<float4*>(p)     = make_float4(a0.x*inv, a0.y*inv, a0.z*inv, a0.w*inv);
    *reinterpret_cast<float4*>(p + 4) = make_float4(a1.x*inv, a1.y*inv, a1.z*inv, a1.w*inv);
}

// ---------------- recurrence pass 1 (fused k-norm, occupancy 3) ---------------
__global__ void __launch_bounds__(512, 3) pass1_kernel()
{
    const int c = blockIdx.x, bh = blockIdx.y;
    const int b = bh >> 4, h = bh & 15;
    const int tid = threadIdx.x;
    const int w = tid >> 5, l = tid & 31;
    __shared__ __align__(16) float ks[CHUNK*HD];
    __shared__ __align__(16) float vs[CHUNK*HD];
    __shared__ float aa[CHUNK], bbs[CHUNK];

    const int row0 = b*SS + c*CHUNK;
    for (int idx = tid; idx < CHUNK*16; idx += 512){
        const int t = idx >> 4, c4 = (idx & 15) * 4;
        const size_t go = (size_t)(row0 + t)*HH + h*HD + c4;
        *reinterpret_cast<float4*>(&ks[t*HD + c4]) = *reinterpret_cast<const float4*>(&g_k[go]);
        *reinterpret_cast<float4*>(&vs[t*HD + c4]) = *reinterpret_cast<const float4*>(&g_v[go]);
    }
    if (tid < CHUNK){
        aa[tid]  = g_alpha[(row0 + tid)*NH + h];
        bbs[tid] = g_beta [(row0 + tid)*NH + h];
    }
    __syncthreads();
    l2norm_smem(ks, w, l);
    __syncthreads();

    float M[4][2], Cc[4][2];
    #pragma unroll
    for (int r=0;r<4;r++){ M[r][0]=1.f; M[r][1]=1.f; Cc[r][0]=0.f; Cc[r][1]=0.f; }

    #pragma unroll 2
    for (int t=0;t<CHUNK;++t){
        const float a = aa[t], bt = bbs[t], abp = a*bt;
        const float kj0 = ks[t*HD + l], kj1 = ks[t*HD + l + 32];
        #pragma unroll
        for (int r=0;r<4;r++){
            const int i = w*4 + r;
            const float ki = ks[t*HD + i];
            const float bvi = bt * vs[t*HD + i];
            const float abki = abp * ki;
            const float m0 = fmaf(-abki, kj0, a);
            const float m1 = fmaf(-abki, kj1, a);
            M[r][0] *= m0;  M[r][1] *= m1;
            Cc[r][0] = fmaf(m0, Cc[r][0], bvi*kj0);
            Cc[r][1] = fmaf(m1, Cc[r][1], bvi*kj1);
        }
    }
    const size_t ob = ((size_t)bh*NCHUNK + c) * SE;
    #pragma unroll
    for (int r=0;r<4;r++){
        const int i = w*4 + r;
        g_M [ob + i*HD + l]      = M[r][0];
        g_M [ob + i*HD + l + 32] = M[r][1];
        g_Cc[ob + i*HD + l]      = Cc[r][0];
        g_Cc[ob + i*HD + l + 32] = Cc[r][1];
    }
}

// ---------------- serial scan: batch-load all chunks, serial FMA chain -------
__global__ void __launch_bounds__(512, 2) scan_kernel()
{
    const int e = blockIdx.x*512 + threadIdx.x;       // 0 .. BHDIM*SE-1
    const int bh = e >> 12;                           // /SE
    const int elem = e & (SE-1);
    const size_t base = (size_t)bh*NCHUNK*SE + elem;

    float m[NCHUNK], cc[NCHUNK];
    #pragma unroll
    for (int c = 0; c < NCHUNK; ++c){
        m[c]  = g_M [base + (size_t)c*SE];
        cc[c] = g_Cc[base + (size_t)c*SE];
    }
    float s = 0.f;
    #pragma unroll
    for (int c = 0; c < NCHUNK; ++c){
        g_S0[base + (size_t)c*SE] = s;
        s = fmaf(m[c], s, cc[c]);
    }
}

// ---------------- recurrence pass 2 (fused k,q normalization) -----------------
#define P2_SMEM (4*CHUNK*HD*4 + 2*CHUNK*4)   // 66048 B
__global__ void __launch_bounds__(512) pass2_kernel()
{
    const int c = blockIdx.x, bh = blockIdx.y;
    const int b = bh >> 4, h = bh & 15;
    const int tid = threadIdx.x;
    const int w = tid >> 5, l = tid & 31;
    extern __shared__ __align__(16) float p2s[];
    float* ks  = p2s;
    float* vs  = p2s + CHUNK*HD;
    float* qs  = p2s + 2*CHUNK*HD;
    float* outs= p2s + 3*CHUNK*HD;
    float* aa  = p2s + 4*CHUNK*HD;
    float* bbs = aa + CHUNK;

    const int row0 = b*SS + c*CHUNK;
    for (int idx = tid; idx < CHUNK*16; idx += 512){
        const int t = idx >> 4, c4 = (idx & 15) * 4;
        const size_t go = (size_t)(row0 + t)*HH + h*HD + c4;
        *reinterpret_cast<float4*>(&ks[t*HD + c4]) = *reinterpret_cast<const float4*>(&g_k[go]);
        *reinterpret_cast<float4*>(&vs[t*HD + c4]) = *reinterpret_cast<const float4*>(&g_v[go]);
        *reinterpret_cast<float4*>(&qs[t*HD + c4]) = *reinterpret_cast<const float4*>(&g_q[go]);
    }
    if (tid < CHUNK){
        aa[tid]  = g_alpha[(row0 + tid)*NH + h];
        bbs[tid] = g_beta [(row0 + tid)*NH + h];
    }

    float st[4][2];
    const size_t sbg = ((size_t)bh*NCHUNK + c) * SE;
    #pragma unroll
    for (int r=0;r<4;r++){
        const int i = w*4 + r;
        st[r][0] = g_S0[sbg + i*HD + l];
        st[r][1] = g_S0[sbg + i*HD + l + 32];
    }
    __syncthreads();
    l2norm_smem(ks, w, l);
    l2norm_smem(qs, w, l);
    __syncthreads();

    #pragma unroll 2
    for (int t=0;t<CHUNK;++t){
        const float a = aa[t], bt = bbs[t], abp = a*bt;
        const float kj0 = ks[t*HD + l], kj1 = ks[t*HD + l + 32];
        const float qj0 = qs[t*HD + l], qj1 = qs[t*HD + l + 32];
        float p[4];
        #pragma unroll
        for (int r=0;r<4;r++){
            const int i = w*4 + r;
            const float ki = ks[t*HD + i];
            const float bvi = bt * vs[t*HD + i];
            const float abki = abp * ki;
            const float m0 = fmaf(-abki, kj0, a);
            const float m1 = fmaf(-abki, kj1, a);
            st[r][0] = fmaf(m0, st[r][0], bvi*kj0);
            st[r][1] = fmaf(m1, st[r][1], bvi*kj1);
            p[r] = fmaf(st[r][0], qj0, st[r][1]*qj1);
        }
        #pragma unroll
        for (int o=16;o;o>>=1){
            p[0] += __shfl_xor_sync(0xffffffffu, p[0], o);
            p[1] += __shfl_xor_sync(0xffffffffu, p[1], o);
            p[2] += __shfl_xor_sync(0xffffffffu, p[2], o);
            p[3] += __shfl_xor_sync(0xffffffffu, p[3], o);
        }
        if (l < 4) outs[t*HD + w*4 + l] = p[l];
    }
    __syncthreads();
    for (int idx = tid; idx < CHUNK*16; idx += 512){
        const int t = idx >> 4, c4 = (idx & 15) * 4;
        const size_t go = (size_t)(row0 + t)*HH + h*HD + c4;
        *reinterpret_cast<float4*>(&g_attn[go]) = *reinterpret_cast<const float4*>(&outs[t*HD + c4]);
    }
}

// ---------------- LayerNorm + SiLU-gate + fp16 split (fused, vectorized) -----
__global__ void __launch_bounds__(256) ln_gate_kernel(
    const float* __restrict__ lng, const float* __restrict__ lnb)
{
    const int r = blockIdx.x, tid = threadIdx.x;
    __shared__ __align__(16) float xs[HH];
    __shared__ float red[8];
    const float* row = g_attn + (size_t)r*HH;
    float s = 0.f;
    for (int i = tid*4; i < HH; i += 256*4){
        float4 v = *reinterpret_cast<const float4*>(row + i);
        *reinterpret_cast<float4*>(&xs[i]) = v;
        s += (v.x + v.y) + (v.z + v.w);
    }
    #pragma unroll
    for (int o=16;o;o>>=1) s += __shfl_xor_sync(0xffffffffu, s, o);
    if ((tid & 31) == 0) red[tid>>5] = s;
    __syncthreads();
    float tot = red[0]+red[1]+red[2]+red[3]+red[4]+red[5]+red[6]+red[7];
    const float mu = tot * (1.f/HH);
    __syncthreads();
    float vsum = 0.f;
    for (int i = tid*4; i < HH; i += 256*4){
        float4 v = *reinterpret_cast<const float4*>(&xs[i]);
        float d0 = v.x-mu, d1 = v.y-mu, d2 = v.z-mu, d3 = v.w-mu;
        vsum = fmaf(d0,d0, fmaf(d1,d1, fmaf(d2,d2, fmaf(d3,d3, vsum))));
    }
    #pragma unroll
    for (int o=16;o;o>>=1) vsum += __shfl_xor_sync(0xffffffffu, vsum, o);
    if ((tid & 31) == 0) red[tid>>5] = vsum;
    __syncthreads();
    float vtot = red[0]+red[1]+red[2]+red[3]+red[4]+red[5]+red[6]+red[7];
    const float rstd = rsqrtf(vtot*(1.f/HH) + 1e-5f);
    for (int i=tid*4;i<HH;i+=256*4){
        float4 gv = *reinterpret_cast<const float4*>(g_g + (size_t)r*HH + i);
        float4 lg = *reinterpret_cast<const float4*>(lng + i);
        float4 lb = *reinterpret_cast<const float4*>(lnb + i);
        float4 xv = *reinterpret_cast<const float4*>(&xs[i]);
        float4 yv;
        yv.x = ((xv.x-mu)*rstd*lg.x + lb.x) * gv.x;
        yv.y = ((xv.y-mu)*rstd*lg.y + lb.y) * gv.y;
        yv.z = ((xv.z-mu)*rstd*lg.z + lb.z) * gv.z;
        yv.w = ((xv.w-mu)*rstd*lg.w + lb.w) * gv.w;
        split4h(yv, g_ahi + (size_t)r*HH + i, g_alo + (size_t)r*HH + i);
    }
}

// ---------------- launch -----------------------------------------------------
extern "C" void kernel_launch(void* const* d_in, const int* in_sizes, int n_in,
                              void* d_out, int out_size)
{
    const float* x   = (const float*)d_in[0];
    const float* Wq  = (const float*)d_in[1];
    const float* Wk  = (const float*)d_in[2];
    const float* Wv  = (const float*)d_in[3];
    const float* Wa  = (const float*)d_in[4];
    const float* ba  = (const float*)d_in[5];
    const float* Wb  = (const float*)d_in[6];
    const float* bb  = (const float*)d_in[7];
    const float* Wg  = (const float*)d_in[8];
    const float* Wo  = (const float*)d_in[9];
    const float* lng = (const float*)d_in[10];
    const float* lnb = (const float*)d_in[11];
    float* out = (float*)d_out;

    cudaFuncSetAttribute(mm_kernel, cudaFuncAttributeMaxDynamicSharedMemorySize, MM_SMEM);
    cudaFuncSetAttribute(pass2_kernel, cudaFuncAttributeMaxDynamicSharedMemorySize, P2_SMEM);

    cvt_all_kernel<<<(CVT_TOT+255)/256, 256>>>(x, Wq, Wk, Wv, Wg, Wo, Wa, Wb);
    mm_kernel<<<dim3(33, 64), 256, MM_SMEM>>>(0, nullptr, ba, bb);  // QKVG + alpha/beta
    pass1_kernel<<<dim3(NCHUNK, BHDIM), 512>>>();
    scan_kernel<<<(BHDIM*SE)/512, 512>>>();
    pass2_kernel<<<dim3(NCHUNK, BHDIM), 512, P2_SMEM>>>();
    ln_gate_kernel<<<NROWS, 256>>>(lng, lnb);
    mm_kernel<<<dim3(8, 64), 256, MM_SMEM>>>(1, out, nullptr, nullptr);
}